// round 14
// baseline (speedup 1.0000x reference)
#include <cuda_runtime.h>
#include <cuda_fp16.h>
#include <math.h>
#include <stdint.h>

// Problem dims
#define BD   512
#define SD   128
#define NED  8192
#define EDD  128
#define DDD  32
#define IND  160
#define HD   512
#define G4D  2048
#define NDD  8
#define PLD  5

#define OUT_PRED_D (512u*8192u*5u)
#define OUT_LOSS   (OUT_PRED_D + 512u*8u*5u)
#define OUT_DC     (OUT_LOSS + 1u)

// ---------------- device scratch ----------------
__device__ float g_P[(NED+1)*G4D];
__device__ float g_Q[(NDD+1)*G4D];
__device__ __half g_whh_fhi[G4D*HD], g_whh_flo[G4D*HD];
__device__ __half g_hh[2][BD*HD], g_hl[2][BD*HD];
__device__ __half g_link_fhi[(NED+1)*EDD], g_link_flo[(NED+1)*EDD];
__device__ __half g_wih_fhi[G4D*EDD], g_wih_flo[G4D*EDD];
__device__ __half g_qhi[BD*EDD], g_qlo[BD*EDD];
__device__ float g_hfp[BD*HD];
__device__ float g_z1[BD*HD], g_z2[BD*HD];
__device__ float g_logits[BD*NDD];
__device__ volatile unsigned g_flag[4 * 32 * 32];

__device__ __forceinline__ float sigmf(float x) { return 1.0f / (1.0f + expf(-x)); }

__device__ __forceinline__ void h16_split(float v, __half& hi, __half& lo) {
    hi = __float2half_rn(v);
    float r = v - __half2float(hi);
    lo = __float2half_rn(r * 1024.0f);
}

__device__ __forceinline__ uint32_t smem_u32(const void* p) {
    uint32_t a;
    asm("{ .reg .u64 t; cvta.to.shared.u64 t, %1; cvt.u32.u64 %0, t; }" : "=r"(a) : "l"(p));
    return a;
}
__device__ __forceinline__ void cp16(uint32_t dst, const void* src) {
    asm volatile("cp.async.cg.shared.global [%0], [%1], 16;" :: "r"(dst), "l"(src));
}
__device__ __forceinline__ void ldsm4(uint32_t* r, uint32_t addr) {
    asm volatile("ldmatrix.sync.aligned.m8n8.x4.shared.b16 {%0,%1,%2,%3}, [%4];"
                 : "=r"(r[0]), "=r"(r[1]), "=r"(r[2]), "=r"(r[3]) : "r"(addr));
}
#define CP_COMMIT() asm volatile("cp.async.commit_group;" ::: "memory")
#define CP_WAIT0()  asm volatile("cp.async.wait_group 0;" ::: "memory")
#define CP_WAIT1()  asm volatile("cp.async.wait_group 1;" ::: "memory")
#define BARN(id, n) asm volatile("bar.sync %0, %1;" :: "r"(id), "r"(n) : "memory")

#define MMAH(d, a, b) \
    asm volatile("mma.sync.aligned.m16n8k16.row.col.f32.f16.f16.f32 " \
                 "{%0,%1,%2,%3},{%4,%5,%6,%7},{%8,%9},{%0,%1,%2,%3};" \
                 : "+f"(d[0]), "+f"(d[1]), "+f"(d[2]), "+f"(d[3]) \
                 : "r"(a[0]), "r"(a[1]), "r"(a[2]), "r"(a[3]), "r"(b[0]), "r"(b[1]))

// ---------------------------------------------------------------------------
__global__ void k_init() {
    int i = blockIdx.x * blockDim.x + threadIdx.x;
    if (i < 4 * 32 * 32) g_flag[i] = 0u;
}

__global__ void k_split(const float* __restrict__ whh, const float* __restrict__ wih,
                        const float* __restrict__ link) {
    int i = blockIdx.x * blockDim.x + threadIdx.x;
    int stride = gridDim.x * blockDim.x;
    for (int idx = i; idx < G4D*HD; idx += stride) {
        __half hi, lo; h16_split(whh[idx], hi, lo);
        g_whh_fhi[idx] = hi; g_whh_flo[idx] = lo;
    }
    for (int idx = i; idx < G4D*EDD; idx += stride) {
        int n = idx >> 7, k = idx & 127;
        __half hi, lo; h16_split(wih[n * IND + k], hi, lo);
        g_wih_fhi[idx] = hi; g_wih_flo[idx] = lo;
    }
    for (int idx = i; idx < (NED+1)*EDD; idx += stride) {
        __half hi, lo; h16_split(link[idx], hi, lo);
        g_link_fhi[idx] = hi; g_link_flo[idx] = lo;
    }
}

__global__ void k_q(const float* __restrict__ dire, const float* __restrict__ wih,
                    const float* __restrict__ bih, const float* __restrict__ bhh) {
    int idx = blockIdx.x * blockDim.x + threadIdx.x;
    if (idx >= (NDD+1) * G4D) return;
    int d = idx / G4D, n = idx - d * G4D;
    float acc = bih[n] + bhh[n];
#pragma unroll 8
    for (int k = 0; k < DDD; k++) acc += dire[d * DDD + k] * wih[n * IND + EDD + k];
    g_Q[idx] = acc;
}

// ---------------------------------------------------------------------------
// K-pe (fp16 2-term): P = link_emb @ Wih_link^T. M=8193, N=2048, K=128.
// ---------------------------------------------------------------------------
#define PASTR 20
#define PA_LO 2560
#define PB_HI 5120
#define PB_LO 6400
#define PBUFW 7680
#define PE_SMEM (2 * PBUFW * 4)

__global__ void __launch_bounds__(256, 1) k_pe() {
    extern __shared__ float psm[];
    const uint32_t sbase = smem_u32(psm);
    const int tid = threadIdx.x;
    const int lane = tid & 31, wid = tid >> 5;
    const int gid = lane >> 2, tig = lane & 3;
    const int mBase = blockIdx.x * 128, nBase = blockIdx.y * 64;
    const int warpM = (wid >> 1) * 32, warpN = (wid & 1) * 32;

    const uint32_t aOff = (uint32_t)(((warpM + (lane & 7) + ((lane >> 3) & 1) * 8) * PASTR
                                     + (lane >> 4) * 4) * 4);
    const uint32_t bOff = (uint32_t)(((warpN + (lane & 7) + ((lane >> 4) & 1) * 8) * PASTR
                                     + ((lane >> 3) & 1) * 4) * 4);

    float D[2][4][4], E[2][4][4];
#pragma unroll
    for (int mt = 0; mt < 2; mt++)
#pragma unroll
        for (int nt = 0; nt < 4; nt++)
#pragma unroll
            for (int r = 0; r < 4; r++) { D[mt][nt][r] = 0.f; E[mt][nt][r] = 0.f; }

    auto load = [&](int cc, int buf) {
        const int kb = cc * 32;
        const uint32_t bu = sbase + (uint32_t)buf * (PBUFW * 4);
#pragma unroll
        for (int t = 0; t < 6; t++) {
            int id = tid + t * 256;
            const __half* src;
            uint32_t dst;
            if (id < 1024) {
                int isLo = id >> 9, rem = id & 511;
                int r = rem >> 2, t4 = rem & 3;
                int rg = mBase + r; if (rg > NED) rg = NED;
                src = (isLo ? g_link_flo : g_link_fhi) + (size_t)rg * EDD + kb + t4 * 8;
                dst = bu + (uint32_t)(((isLo ? PA_LO : 0) + r * PASTR + t4 * 4) * 4);
            } else {
                int id2 = id - 1024;
                int isLo = id2 >> 8, rem = id2 & 255;
                int r = rem >> 2, t4 = rem & 3;
                src = (isLo ? g_wih_flo : g_wih_fhi) + (size_t)(nBase + r) * EDD + kb + t4 * 8;
                dst = bu + (uint32_t)(((isLo ? PB_LO : PB_HI) + r * PASTR + t4 * 4) * 4);
            }
            cp16(dst, src);
        }
        CP_COMMIT();
    };

    load(0, 0);
#pragma unroll 1
    for (int cc = 0; cc < 4; cc++) {
        const int buf = cc & 1;
        CP_WAIT0();
        __syncthreads();
        if (cc < 3) load(cc + 1, buf ^ 1);

        const uint32_t bb = sbase + (uint32_t)buf * (PBUFW * 4);
        const uint32_t aHi = bb + aOff, aLo = bb + (uint32_t)(PA_LO * 4) + aOff;
        const uint32_t bHi = bb + (uint32_t)(PB_HI * 4) + bOff;
        const uint32_t bLo = bb + (uint32_t)(PB_LO * 4) + bOff;
#pragma unroll
        for (int ksub = 0; ksub < 2; ksub++) {
            const uint32_t k0 = (uint32_t)(ksub * 8 * 4);
            uint32_t ahi[2][4], alo[2][4];
            ldsm4(ahi[0], aHi + k0);
            ldsm4(ahi[1], aHi + k0 + 16 * PASTR * 4);
            ldsm4(alo[0], aLo + k0);
            ldsm4(alo[1], aLo + k0 + 16 * PASTR * 4);
            uint32_t bhi[4][2], blo[4][2];
            {
                uint32_t t4[4];
                ldsm4(t4, bHi + k0);
                bhi[0][0] = t4[0]; bhi[0][1] = t4[1]; bhi[1][0] = t4[2]; bhi[1][1] = t4[3];
                ldsm4(t4, bHi + k0 + 16 * PASTR * 4);
                bhi[2][0] = t4[0]; bhi[2][1] = t4[1]; bhi[3][0] = t4[2]; bhi[3][1] = t4[3];
                ldsm4(t4, bLo + k0);
                blo[0][0] = t4[0]; blo[0][1] = t4[1]; blo[1][0] = t4[2]; blo[1][1] = t4[3];
                ldsm4(t4, bLo + k0 + 16 * PASTR * 4);
                blo[2][0] = t4[0]; blo[2][1] = t4[1]; blo[3][0] = t4[2]; blo[3][1] = t4[3];
            }
#pragma unroll
            for (int mt = 0; mt < 2; mt++)
#pragma unroll
                for (int nt = 0; nt < 4; nt++) {
                    MMAH(D[mt][nt], ahi[mt], bhi[nt]);
                    MMAH(E[mt][nt], ahi[mt], blo[nt]);
                    MMAH(E[mt][nt], alo[mt], bhi[nt]);
                }
        }
    }

#pragma unroll
    for (int mt = 0; mt < 2; mt++)
#pragma unroll
        for (int nt = 0; nt < 4; nt++) {
            int r0 = mBase + warpM + mt * 16 + gid;
            int n0 = nBase + warpN + nt * 8 + 2 * tig;
            float v0 = D[mt][nt][0] + E[mt][nt][0] * 0.0009765625f;
            float v1 = D[mt][nt][1] + E[mt][nt][1] * 0.0009765625f;
            float v2 = D[mt][nt][2] + E[mt][nt][2] * 0.0009765625f;
            float v3 = D[mt][nt][3] + E[mt][nt][3] * 0.0009765625f;
            if (r0 < NED + 1) {
                g_P[(size_t)r0 * G4D + n0]     = v0;
                g_P[(size_t)r0 * G4D + n0 + 1] = v1;
            }
            if (r0 + 8 < NED + 1) {
                g_P[(size_t)(r0+8) * G4D + n0]   = v2;
                g_P[(size_t)(r0+8) * G4D + n0+1] = v3;
            }
        }
}

// ---------------------------------------------------------------------------
// K-rnn: persistent recurrence (round-11 pipeline + dual-region reduce)
// ---------------------------------------------------------------------------
#define BSTR 260
#define BW_LO 16640
#define AW0   33280
#define AKG   10240
#define ABUF  5120
#define A_LOW 2560
#define ASTR  20
#define REDW  8704
#define PK_SMEM (53760 * 4)

__global__ void __launch_bounds__(512, 1) k_rnn(const int* __restrict__ inputs,
                                                const int* __restrict__ dirs) {
    extern __shared__ float sm[];
    uint32_t* smw = (uint32_t*)sm;
    const uint32_t sbase = smem_u32(sm);
    const int tid = threadIdx.x;
    const int lane = tid & 31, wid = tid >> 5;
    const int kg = wid >> 3, wid8 = wid & 7;
    const int lt = tid & 255;
    const int grp = blockIdx.x;
    const int jt = blockIdx.y;
    const int bBase = blockIdx.x * 128;
    const int jBase = blockIdx.y * 16;
    const int warpM = (wid8 >> 1) * 32, warpN = (wid8 & 1) * 32;

    for (int i = tid; i < 64 * 64; i += 512) {
        int r = i >> 6, q = i & 63;
        int g = r & 3, jl = r >> 2;
        size_t src = ((size_t)(g * HD + jBase + jl)) * HD + q * 8;
        uint4 vh = *(const uint4*)(g_whh_fhi + src);
        uint4 vl = *(const uint4*)(g_whh_flo + src);
        *(uint4*)(smw + r * BSTR + q * 4) = vh;
        *(uint4*)(smw + BW_LO + r * BSTR + q * 4) = vl;
    }
    __syncthreads();

    const uint32_t aOffL = (uint32_t)(((warpM + (lane & 7) + ((lane >> 3) & 1) * 8) * ASTR
                                      + (lane >> 4) * 4) * 4);
    const uint32_t bOffL = (uint32_t)(((warpN + (lane & 7) + ((lane >> 4) & 1) * 8) * BSTR
                                      + ((lane >> 3) & 1) * 4) * 4);
    const uint32_t bHiL = sbase + bOffL;
    const uint32_t bLoL = sbase + (uint32_t)(BW_LO * 4) + bOffL;

    const int bl_ep = tid >> 2;
    const int b_ep = bBase + bl_ep;
    const int j0 = (tid & 3) * 4;
    float cst[4] = {0.f, 0.f, 0.f, 0.f};

    for (int s = 0; s < SD; s++) {
        const int inp = inputs[b_ep * SD + s];
        const int dr  = dirs[b_ep * SD + s];
        float gb[16];
#pragma unroll
        for (int g = 0; g < 4; g++) {
            float4 pv = *(const float4*)(g_P + (size_t)inp * G4D + g * HD + jBase + j0);
            float4 qv = *(const float4*)(g_Q + (size_t)dr * G4D + g * HD + jBase + j0);
            gb[g * 4 + 0] = pv.x + qv.x;
            gb[g * 4 + 1] = pv.y + qv.y;
            gb[g * 4 + 2] = pv.z + qv.z;
            gb[g * 4 + 3] = pv.w + qv.w;
        }

        float D[2][4][4], E[2][4][4];
#pragma unroll
        for (int mt = 0; mt < 2; mt++)
#pragma unroll
            for (int nt = 0; nt < 4; nt++)
#pragma unroll
                for (int r = 0; r < 4; r++) { D[mt][nt][r] = 0.f; E[mt][nt][r] = 0.f; }

        if (s > 0) {
            const __half* __restrict__ hh = g_hh[s & 1];
            const __half* __restrict__ hl = g_hl[s & 1];
            auto load_chunk = [&](int cc, int buf) {
                const int kb = kg * 256 + cc * 32;
                const uint32_t bu = sbase + (uint32_t)((AW0 + kg * AKG + buf * ABUF) * 4);
#pragma unroll
                for (int t = 0; t < 4; t++) {
                    int id = lt + t * 256;
                    int isLo = id >> 9;
                    int rem = id & 511;
                    int r = rem >> 2, t4 = rem & 3;
                    const __half* src = (isLo ? hl : hh) + (size_t)(bBase + r) * HD + kb + t4 * 8;
                    uint32_t dst = bu + (uint32_t)(((isLo ? A_LOW : 0) + r * ASTR + t4 * 4) * 4);
                    cp16(dst, src);
                }
                CP_COMMIT();
            };

            load_chunk(0, 0);
#pragma unroll 1
            for (int cc = 0; cc < 8; cc++) {
                const int buf = cc & 1;
                BARN(1 + kg, 256);
                if (cc < 7) {
                    load_chunk(cc + 1, buf ^ 1);
                    CP_WAIT1();
                } else {
                    CP_WAIT0();
                }
                BARN(3 + kg, 256);

                const uint32_t aHiBase = sbase + (uint32_t)((AW0 + kg * AKG + buf * ABUF) * 4) + aOffL;
                const uint32_t aLoBase = aHiBase + (uint32_t)(A_LOW * 4);
                const int kwBase = kg * 128 + cc * 16;
#pragma unroll
                for (int ksub = 0; ksub < 2; ksub++) {
                    const int k0 = ksub * 8;
                    uint32_t ahi[2][4], alo[2][4];
                    ldsm4(ahi[0], aHiBase + k0 * 4);
                    ldsm4(ahi[1], aHiBase + k0 * 4 + 16 * ASTR * 4);
                    ldsm4(alo[0], aLoBase + k0 * 4);
                    ldsm4(alo[1], aLoBase + k0 * 4 + 16 * ASTR * 4);
                    uint32_t bhi[4][2], blo[4][2];
                    {
                        const uint32_t kwb = (uint32_t)((kwBase + k0) * 4);
                        uint32_t t4[4];
                        ldsm4(t4, bHiL + kwb);
                        bhi[0][0] = t4[0]; bhi[0][1] = t4[1]; bhi[1][0] = t4[2]; bhi[1][1] = t4[3];
                        ldsm4(t4, bHiL + kwb + 16 * BSTR * 4);
                        bhi[2][0] = t4[0]; bhi[2][1] = t4[1]; bhi[3][0] = t4[2]; bhi[3][1] = t4[3];
                        ldsm4(t4, bLoL + kwb);
                        blo[0][0] = t4[0]; blo[0][1] = t4[1]; blo[1][0] = t4[2]; blo[1][1] = t4[3];
                        ldsm4(t4, bLoL + kwb + 16 * BSTR * 4);
                        blo[2][0] = t4[0]; blo[2][1] = t4[1]; blo[3][0] = t4[2]; blo[3][1] = t4[3];
                    }
#pragma unroll
                    for (int mt = 0; mt < 2; mt++)
#pragma unroll
                        for (int nt = 0; nt < 4; nt++) {
                            MMAH(D[mt][nt], ahi[mt], bhi[nt]);
                            MMAH(E[mt][nt], ahi[mt], blo[nt]);
                            MMAH(E[mt][nt], alo[mt], bhi[nt]);
                        }
                }
            }
#pragma unroll
            for (int mt = 0; mt < 2; mt++)
#pragma unroll
                for (int nt = 0; nt < 4; nt++)
#pragma unroll
                    for (int r = 0; r < 4; r++)
                        D[mt][nt][r] += E[mt][nt][r] * 0.0009765625f;
        }

        __syncthreads();
        float* red = sm + AW0;
        if (s > 0) {
            // both kgroups write their own region; epilogue sums them
            const int gid = lane >> 2, tig = lane & 3;
            float* myred = red + kg * REDW;
#pragma unroll
            for (int mt = 0; mt < 2; mt++)
#pragma unroll
                for (int nt = 0; nt < 4; nt++) {
                    int r0 = warpM + mt * 16 + gid;
                    int n0 = warpN + nt * 8 + 2 * tig;
                    myred[r0 * 68 + n0]           = D[mt][nt][0];
                    myred[r0 * 68 + n0 + 1]       = D[mt][nt][1];
                    myred[(r0 + 8) * 68 + n0]     = D[mt][nt][2];
                    myred[(r0 + 8) * 68 + n0 + 1] = D[mt][nt][3];
                }
            __syncthreads();
        }

        // ---- fused LSTM epilogue ----
        {
            __half hhi[4], hlo[4];
            float hf[4];
#pragma unroll
            for (int jj = 0; jj < 4; jj++) {
                float gi = gb[0 * 4 + jj];
                float gf = gb[1 * 4 + jj];
                float gg = gb[2 * 4 + jj];
                float go = gb[3 * 4 + jj];
                if (s > 0) {
                    int nb = (j0 + jj) * 4;
                    int base = bl_ep * 68 + nb;
                    gi += red[base + 0] + red[REDW + base + 0];
                    gf += red[base + 1] + red[REDW + base + 1];
                    gg += red[base + 2] + red[REDW + base + 2];
                    go += red[base + 3] + red[REDW + base + 3];
                }
                float cn = sigmf(gf) * cst[jj] + sigmf(gi) * tanhf(gg);
                cst[jj] = cn;
                float h = sigmf(go) * tanhf(cn);
                hf[jj] = h;
                h16_split(h, hhi[jj], hlo[jj]);
            }
            __half* hho = g_hh[(s + 1) & 1];
            __half* hlo_ = g_hl[(s + 1) & 1];
            size_t off = (size_t)b_ep * HD + jBase + j0;
            *(__half2*)(hho + off)     = __halves2half2(hhi[0], hhi[1]);
            *(__half2*)(hho + off + 2) = __halves2half2(hhi[2], hhi[3]);
            *(__half2*)(hlo_ + off)     = __halves2half2(hlo[0], hlo[1]);
            *(__half2*)(hlo_ + off + 2) = __halves2half2(hlo[2], hlo[3]);
            if (s == SD - 1)
                *(float4*)(g_hfp + off) = make_float4(hf[0], hf[1], hf[2], hf[3]);
        }

        // ---- flag-vector barrier over this b-group (32 CTAs) ----
        __threadfence();
        __syncthreads();
        if (tid == 0) g_flag[(grp * 32 + jt) * 32] = (unsigned)(s + 1);
        if (tid < 32) {
            while (g_flag[(grp * 32 + tid) * 32] < (unsigned)(s + 1)) { }
        }
        __threadfence();
        __syncthreads();
    }
}

// ---------------------------------------------------------------------------
// MLP layers (fp32)
// ---------------------------------------------------------------------------
__global__ void k_mlp(int which, const float* __restrict__ W, const float* __restrict__ bias) {
    __shared__ float sa[32][33];
    __shared__ float swm[32][33];
    const int tid = threadIdx.x;
    const int tx = tid & 15, ty = tid >> 4;
    const int mBase = blockIdx.x * 32;
    const int nBase = blockIdx.y * 32;
    const float* __restrict__ A = (which == 0) ? g_hfp : g_z1;
    float* __restrict__ out = (which == 0) ? g_z1 : g_z2;

    float acc[4] = {0.f, 0.f, 0.f, 0.f};
    for (int kb = 0; kb < HD; kb += 32) {
#pragma unroll
        for (int i = 0; i < 4; i++) {
            int idx = tid + i * 256;
            int r = idx >> 5, c = idx & 31;
            sa[r][c]  = A[(mBase + r) * HD + kb + c];
            swm[r][c] = W[(nBase + r) * HD + kb + c];
        }
        __syncthreads();
#pragma unroll
        for (int kk = 0; kk < 32; kk++) {
            float a0 = sa[ty][kk], a1 = sa[ty + 16][kk];
            float w0 = swm[tx][kk], w1 = swm[tx + 16][kk];
            acc[0] += a0 * w0; acc[1] += a0 * w1;
            acc[2] += a1 * w0; acc[3] += a1 * w1;
        }
        __syncthreads();
    }
#pragma unroll
    for (int bi = 0; bi < 2; bi++)
#pragma unroll
        for (int ni = 0; ni < 2; ni++) {
            int m = mBase + ty + bi * 16;
            int n = nBase + tx + ni * 16;
            float v = acc[bi * 2 + ni] + bias[n];
            out[m * HD + n] = fmaxf(v, 0.0f);
        }
}

__global__ void k_logits(const float* __restrict__ W3, const float* __restrict__ b3) {
    int idx = blockIdx.x * blockDim.x + threadIdx.x;
    if (idx >= BD * NDD) return;
    int b = idx >> 3, n = idx & 7;
    const float4* z = (const float4*)(g_z2 + b * HD);
    const float4* w = (const float4*)(W3 + n * HD);
    float acc = b3[n];
#pragma unroll 4
    for (int k = 0; k < HD / 4; k++) {
        float4 zv = z[k], wv = w[k];
        acc += zv.x * wv.x + zv.y * wv.y + zv.z * wv.z + zv.w * wv.w;
    }
    g_logits[idx] = acc;
}

// ---------------------------------------------------------------------------
// Head: softmax/top2/loss/dc + query build (fp16-split for k_sim) + pred_d copy
// ---------------------------------------------------------------------------
__global__ void k_head(const int* __restrict__ inputs, const int* __restrict__ goal,
                       const int* __restrict__ locd, const float* __restrict__ link,
                       const float* __restrict__ dire, const float* __restrict__ pdr,
                       float* __restrict__ out) {
    int b = threadIdx.x;
    float p[NDD];
    float mx = -1e30f;
#pragma unroll
    for (int n = 0; n < NDD; n++) { p[n] = g_logits[b * NDD + n]; mx = fmaxf(mx, p[n]); }
    float se = 0.0f;
#pragma unroll
    for (int n = 0; n < NDD; n++) se += expf(p[n] - mx);
    float lse = mx + logf(se);
#pragma unroll
    for (int n = 0; n < NDD; n++) p[n] -= lse;

    float mx2 = -1e30f;
#pragma unroll
    for (int n = 0; n < NDD; n++) mx2 = fmaxf(mx2, p[n]);
    float se2 = 0.0f;
#pragma unroll
    for (int n = 0; n < NDD; n++) se2 += expf(p[n] - mx2);
    float lse2 = mx2 + logf(se2);

    int i0 = 0; float v0 = p[0];
#pragma unroll
    for (int n = 1; n < NDD; n++) if (p[n] > v0) { v0 = p[n]; i0 = n; }
    int i1 = -1; float v1 = -1e30f;
#pragma unroll
    for (int n = 0; n < NDD; n++) if (n != i0 && p[n] > v1) { v1 = p[n]; i1 = n; }

    int last = inputs[b * SD + SD - 1];
    int lbl = locd[(size_t)(last - 1) * NED + goal[b]];
    float lossi = -(p[lbl] - lse2);
    int corr = (i0 == lbl) || (i1 == lbl);

    const float* le = link + (size_t)last * EDD;
    const float* d0 = dire + (i0 + 1) * DDD;
    const float* d1 = dire + (i1 + 1) * DDD;
#pragma unroll 4
    for (int k = 0; k < EDD; k++) {
        float q = le[k];
        if (k < DDD) q += 0.5f * (d0[k] + d1[k]);
        __half hi, lo; h16_split(q, hi, lo);
        g_qhi[b * EDD + k] = hi;
        g_qlo[b * EDD + k] = lo;
    }

    __shared__ float sl[BD];
    __shared__ int sc[BD];
    sl[b] = lossi; sc[b] = corr;
    __syncthreads();
    for (int st = BD / 2; st > 0; st >>= 1) {
        if (b < st) { sl[b] += sl[b + st]; sc[b] += sc[b + st]; }
        __syncthreads();
    }
    if (b == 0) {
        out[OUT_LOSS] = sl[0] * (5.0f / (float)BD);
        out[OUT_DC] = (float)sc[0];
    }
    for (int i = b; i < BD * NDD * PLD; i += BD) out[OUT_PRED_D + i] = pdr[i];
}

// ---------------------------------------------------------------------------
// Sim GEMM (fp16 2-term): sim = query @ link[1:]^T, tiled x5 into pred_hard.
//   M=512 (4 mtiles of 128), N=8192 (128 ntiles of 64), K=128.
// ---------------------------------------------------------------------------
__global__ void __launch_bounds__(256, 1) k_sim(float* __restrict__ out) {
    extern __shared__ float psm[];
    const uint32_t sbase = smem_u32(psm);
    const int tid = threadIdx.x;
    const int lane = tid & 31, wid = tid >> 5;
    const int gid = lane >> 2, tig = lane & 3;
    const int mBase = blockIdx.x * 128, nBase = blockIdx.y * 64;
    const int warpM = (wid >> 1) * 32, warpN = (wid & 1) * 32;

    const uint32_t aOff = (uint32_t)(((warpM + (lane & 7) + ((lane >> 3) & 1) * 8) * PASTR
                                     + (lane >> 4) * 4) * 4);
    const uint32_t bOff = (uint32_t)(((warpN + (lane & 7) + ((lane >> 4) & 1) * 8) * PASTR
                                     + ((lane >> 3) & 1) * 4) * 4);

    float D[2][4][4], E[2][4][4];
#pragma unroll
    for (int mt = 0; mt < 2; mt++)
#pragma unroll
        for (int nt = 0; nt < 4; nt++)
#pragma unroll
            for (int r = 0; r < 4; r++) { D[mt][nt][r] = 0.f; E[mt][nt][r] = 0.f; }

    auto load = [&](int cc, int buf) {
        const int kb = cc * 32;
        const uint32_t bu = sbase + (uint32_t)buf * (PBUFW * 4);
#pragma unroll
        for (int t = 0; t < 6; t++) {
            int id = tid + t * 256;
            const __half* src;
            uint32_t dst;
            if (id < 1024) {
                int isLo = id >> 9, rem = id & 511;
                int r = rem >> 2, t4 = rem & 3;
                src = (isLo ? g_qlo : g_qhi) + (size_t)(mBase + r) * EDD + kb + t4 * 8;
                dst = bu + (uint32_t)(((isLo ? PA_LO : 0) + r * PASTR + t4 * 4) * 4);
            } else {
                int id2 = id - 1024;
                int isLo = id2 >> 8, rem = id2 & 255;
                int r = rem >> 2, t4 = rem & 3;
                src = (isLo ? g_link_flo : g_link_fhi) + (size_t)(nBase + r + 1) * EDD + kb + t4 * 8;
                dst = bu + (uint32_t)(((isLo ? PB_LO : PB_HI) + r * PASTR + t4 * 4) * 4);
            }
            cp16(dst, src);
        }
        CP_COMMIT();
    };

    load(0, 0);
#pragma unroll 1
    for (int cc = 0; cc < 4; cc++) {
        const int buf = cc & 1;
        CP_WAIT0();
        __syncthreads();
        if (cc < 3) load(cc + 1, buf ^ 1);

        const uint32_t bb = sbase + (uint32_t)buf * (PBUFW * 4);
        const uint32_t aHi = bb + aOff, aLo = bb + (uint32_t)(PA_LO * 4) + aOff;
        const uint32_t bHi = bb + (uint32_t)(PB_HI * 4) + bOff;
        const uint32_t bLo = bb + (uint32_t)(PB_LO * 4) + bOff;
#pragma unroll
        for (int ksub = 0; ksub < 2; ksub++) {
            const uint32_t k0 = (uint32_t)(ksub * 8 * 4);
            uint32_t ahi[2][4], alo[2][4];
            ldsm4(ahi[0], aHi + k0);
            ldsm4(ahi[1], aHi + k0 + 16 * PASTR * 4);
            ldsm4(alo[0], aLo + k0);
            ldsm4(alo[1], aLo + k0 + 16 * PASTR * 4);
            uint32_t bhi[4][2], blo[4][2];
            {
                uint32_t t4[4];
                ldsm4(t4, bHi + k0);
                bhi[0][0] = t4[0]; bhi[0][1] = t4[1]; bhi[1][0] = t4[2]; bhi[1][1] = t4[3];
                ldsm4(t4, bHi + k0 + 16 * PASTR * 4);
                bhi[2][0] = t4[0]; bhi[2][1] = t4[1]; bhi[3][0] = t4[2]; bhi[3][1] = t4[3];
                ldsm4(t4, bLo + k0);
                blo[0][0] = t4[0]; blo[0][1] = t4[1]; blo[1][0] = t4[2]; blo[1][1] = t4[3];
                ldsm4(t4, bLo + k0 + 16 * PASTR * 4);
                blo[2][0] = t4[0]; blo[2][1] = t4[1]; blo[3][0] = t4[2]; blo[3][1] = t4[3];
            }
#pragma unroll
            for (int mt = 0; mt < 2; mt++)
#pragma unroll
                for (int nt = 0; nt < 4; nt++) {
                    MMAH(D[mt][nt], ahi[mt], bhi[nt]);
                    MMAH(E[mt][nt], ahi[mt], blo[nt]);
                    MMAH(E[mt][nt], alo[mt], bhi[nt]);
                }
        }
    }

#pragma unroll
    for (int mt = 0; mt < 2; mt++)
#pragma unroll
        for (int nt = 0; nt < 4; nt++) {
            int r0 = mBase + warpM + mt * 16 + gid;
            int n0 = nBase + warpN + nt * 8 + 2 * tig;
            float2 va = make_float2(D[mt][nt][0] + E[mt][nt][0] * 0.0009765625f,
                                    D[mt][nt][1] + E[mt][nt][1] * 0.0009765625f);
            float2 vb = make_float2(D[mt][nt][2] + E[mt][nt][2] * 0.0009765625f,
                                    D[mt][nt][3] + E[mt][nt][3] * 0.0009765625f);
            size_t basea = (size_t)r0 * (NED * PLD) + n0;
            size_t baseb = (size_t)(r0 + 8) * (NED * PLD) + n0;
#pragma unroll
            for (int pl = 0; pl < PLD; pl++) {
                *(float2*)(out + basea + (size_t)pl * NED) = va;
                *(float2*)(out + baseb + (size_t)pl * NED) = vb;
            }
        }
}

// ---------------------------------------------------------------------------
// Launcher
// ---------------------------------------------------------------------------
extern "C" void kernel_launch(void* const* d_in, const int* in_sizes, int n_in,
                              void* d_out, int out_size) {
    const int*   inputs = (const int*)d_in[0];
    const int*   dirs   = (const int*)d_in[1];
    const int*   goal   = (const int*)d_in[2];
    const int*   locd   = (const int*)d_in[3];
    const float* pdr    = (const float*)d_in[4];
    const float* link   = (const float*)d_in[5];
    const float* dire   = (const float*)d_in[6];
    const float* w_ih   = (const float*)d_in[7];
    const float* b_ih   = (const float*)d_in[8];
    const float* w_hh   = (const float*)d_in[9];
    const float* b_hh   = (const float*)d_in[10];
    const float* W1     = (const float*)d_in[11];
    const float* b1     = (const float*)d_in[12];
    const float* W2     = (const float*)d_in[13];
    const float* b2     = (const float*)d_in[14];
    const float* W3     = (const float*)d_in[15];
    const float* b3     = (const float*)d_in[16];
    float* out = (float*)d_out;

    static int smem_set = 0;
    if (!smem_set) {
        cudaFuncSetAttribute(k_rnn, cudaFuncAttributeMaxDynamicSharedMemorySize, PK_SMEM);
        cudaFuncSetAttribute(k_pe, cudaFuncAttributeMaxDynamicSharedMemorySize, PE_SMEM);
        cudaFuncSetAttribute(k_sim, cudaFuncAttributeMaxDynamicSharedMemorySize, PE_SMEM);
        smem_set = 1;
    }

    k_init<<<16, 256>>>();
    k_split<<<512, 256>>>(w_hh, w_ih, link);
    k_q<<<((NDD+1) * G4D + 255) / 256, 256>>>(dire, w_ih, b_ih, b_hh);

    // P = link_emb @ Wih_link^T (fp16 2-term)
    k_pe<<<dim3(65, 32), 256, PE_SMEM>>>();

    // Persistent recurrence
    k_rnn<<<dim3(4, 32), 512, PK_SMEM>>>(inputs, dirs);

    k_mlp<<<dim3(BD / 32, HD / 32), 256>>>(0, W1, b1);
    k_mlp<<<dim3(BD / 32, HD / 32), 256>>>(1, W2, b2);
    k_logits<<<(BD * NDD + 255) / 256, 256>>>(W3, b3);
    k_head<<<1, BD>>>(inputs, goal, locd, link, dire, pdr, out);

    // Sim GEMM (fp16 2-term) + 5x tiling
    k_sim<<<dim3(4, 128), 256, PE_SMEM>>>(out);
}

// round 15
// speedup vs baseline: 1.0124x; 1.0124x over previous
#include <cuda_runtime.h>
#include <cuda_fp16.h>
#include <math.h>
#include <stdint.h>

// Problem dims
#define BD   512
#define SD   128
#define NED  8192
#define EDD  128
#define DDD  32
#define IND  160
#define HD   512
#define G4D  2048
#define NDD  8
#define PLD  5

#define OUT_PRED_D (512u*8192u*5u)
#define OUT_LOSS   (OUT_PRED_D + 512u*8u*5u)
#define OUT_DC     (OUT_LOSS + 1u)

// ---------------- device scratch ----------------
__device__ float g_P[(NED+1)*G4D];
__device__ float g_Q[(NDD+1)*G4D];
__device__ __half g_whh_fhi[G4D*HD], g_whh_flo[G4D*HD];
__device__ __half g_hh[2][BD*HD], g_hl[2][BD*HD];
__device__ __half g_link_fhi[(NED+1)*EDD], g_link_flo[(NED+1)*EDD];
__device__ __half g_wih_fhi[G4D*EDD], g_wih_flo[G4D*EDD];
__device__ __half g_qhi[BD*EDD], g_qlo[BD*EDD];
__device__ float g_hfp[BD*HD];
__device__ float g_z1[BD*HD], g_z2[BD*HD];
__device__ float g_logits[BD*NDD];
__device__ volatile unsigned g_flag[4 * 32 * 32];

__device__ __forceinline__ float sigmf(float x) { return 1.0f / (1.0f + expf(-x)); }

__device__ __forceinline__ void h16_split(float v, __half& hi, __half& lo) {
    hi = __float2half_rn(v);
    float r = v - __half2float(hi);
    lo = __float2half_rn(r * 1024.0f);
}

__device__ __forceinline__ uint32_t smem_u32(const void* p) {
    uint32_t a;
    asm("{ .reg .u64 t; cvta.to.shared.u64 t, %1; cvt.u32.u64 %0, t; }" : "=r"(a) : "l"(p));
    return a;
}
__device__ __forceinline__ void cp16(uint32_t dst, const void* src) {
    asm volatile("cp.async.cg.shared.global [%0], [%1], 16;" :: "r"(dst), "l"(src));
}
__device__ __forceinline__ void ldsm4(uint32_t* r, uint32_t addr) {
    asm volatile("ldmatrix.sync.aligned.m8n8.x4.shared.b16 {%0,%1,%2,%3}, [%4];"
                 : "=r"(r[0]), "=r"(r[1]), "=r"(r[2]), "=r"(r[3]) : "r"(addr));
}
#define CP_COMMIT() asm volatile("cp.async.commit_group;" ::: "memory")
#define CP_WAIT0()  asm volatile("cp.async.wait_group 0;" ::: "memory")
#define CP_WAIT1()  asm volatile("cp.async.wait_group 1;" ::: "memory")
#define BARN(id, n) asm volatile("bar.sync %0, %1;" :: "r"(id), "r"(n) : "memory")

#define MMAH(d, a, b) \
    asm volatile("mma.sync.aligned.m16n8k16.row.col.f32.f16.f16.f32 " \
                 "{%0,%1,%2,%3},{%4,%5,%6,%7},{%8,%9},{%0,%1,%2,%3};" \
                 : "+f"(d[0]), "+f"(d[1]), "+f"(d[2]), "+f"(d[3]) \
                 : "r"(a[0]), "r"(a[1]), "r"(a[2]), "r"(a[3]), "r"(b[0]), "r"(b[1]))

// ---------------------------------------------------------------------------
__global__ void k_init() {
    int i = blockIdx.x * blockDim.x + threadIdx.x;
    if (i < 4 * 32 * 32) g_flag[i] = 0u;
}

__global__ void k_split(const float* __restrict__ whh, const float* __restrict__ wih,
                        const float* __restrict__ link) {
    int i = blockIdx.x * blockDim.x + threadIdx.x;
    int stride = gridDim.x * blockDim.x;
    for (int idx = i; idx < G4D*HD; idx += stride) {
        __half hi, lo; h16_split(whh[idx], hi, lo);
        g_whh_fhi[idx] = hi; g_whh_flo[idx] = lo;
    }
    for (int idx = i; idx < G4D*EDD; idx += stride) {
        int n = idx >> 7, k = idx & 127;
        __half hi, lo; h16_split(wih[n * IND + k], hi, lo);
        g_wih_fhi[idx] = hi; g_wih_flo[idx] = lo;
    }
    for (int idx = i; idx < (NED+1)*EDD; idx += stride) {
        __half hi, lo; h16_split(link[idx], hi, lo);
        g_link_fhi[idx] = hi; g_link_flo[idx] = lo;
    }
}

__global__ void k_q(const float* __restrict__ dire, const float* __restrict__ wih,
                    const float* __restrict__ bih, const float* __restrict__ bhh) {
    int idx = blockIdx.x * blockDim.x + threadIdx.x;
    if (idx >= (NDD+1) * G4D) return;
    int d = idx / G4D, n = idx - d * G4D;
    float acc = bih[n] + bhh[n];
#pragma unroll 8
    for (int k = 0; k < DDD; k++) acc += dire[d * DDD + k] * wih[n * IND + EDD + k];
    g_Q[idx] = acc;
}

// ---------------------------------------------------------------------------
// K-pe (fp16 2-term): P = link_emb @ Wih_link^T. M=8193, N=2048, K=128.
// ---------------------------------------------------------------------------
#define PASTR 20
#define PA_LO 2560
#define PB_HI 5120
#define PB_LO 6400
#define PBUFW 7680
#define PE_SMEM (2 * PBUFW * 4)

__global__ void __launch_bounds__(256, 1) k_pe() {
    extern __shared__ float psm[];
    const uint32_t sbase = smem_u32(psm);
    const int tid = threadIdx.x;
    const int lane = tid & 31, wid = tid >> 5;
    const int gid = lane >> 2, tig = lane & 3;
    const int mBase = blockIdx.x * 128, nBase = blockIdx.y * 64;
    const int warpM = (wid >> 1) * 32, warpN = (wid & 1) * 32;

    const uint32_t aOff = (uint32_t)(((warpM + (lane & 7) + ((lane >> 3) & 1) * 8) * PASTR
                                     + (lane >> 4) * 4) * 4);
    const uint32_t bOff = (uint32_t)(((warpN + (lane & 7) + ((lane >> 4) & 1) * 8) * PASTR
                                     + ((lane >> 3) & 1) * 4) * 4);

    float D[2][4][4], E[2][4][4];
#pragma unroll
    for (int mt = 0; mt < 2; mt++)
#pragma unroll
        for (int nt = 0; nt < 4; nt++)
#pragma unroll
            for (int r = 0; r < 4; r++) { D[mt][nt][r] = 0.f; E[mt][nt][r] = 0.f; }

    auto load = [&](int cc, int buf) {
        const int kb = cc * 32;
        const uint32_t bu = sbase + (uint32_t)buf * (PBUFW * 4);
#pragma unroll
        for (int t = 0; t < 6; t++) {
            int id = tid + t * 256;
            const __half* src;
            uint32_t dst;
            if (id < 1024) {
                int isLo = id >> 9, rem = id & 511;
                int r = rem >> 2, t4 = rem & 3;
                int rg = mBase + r; if (rg > NED) rg = NED;
                src = (isLo ? g_link_flo : g_link_fhi) + (size_t)rg * EDD + kb + t4 * 8;
                dst = bu + (uint32_t)(((isLo ? PA_LO : 0) + r * PASTR + t4 * 4) * 4);
            } else {
                int id2 = id - 1024;
                int isLo = id2 >> 8, rem = id2 & 255;
                int r = rem >> 2, t4 = rem & 3;
                src = (isLo ? g_wih_flo : g_wih_fhi) + (size_t)(nBase + r) * EDD + kb + t4 * 8;
                dst = bu + (uint32_t)(((isLo ? PB_LO : PB_HI) + r * PASTR + t4 * 4) * 4);
            }
            cp16(dst, src);
        }
        CP_COMMIT();
    };

    load(0, 0);
#pragma unroll 1
    for (int cc = 0; cc < 4; cc++) {
        const int buf = cc & 1;
        CP_WAIT0();
        __syncthreads();
        if (cc < 3) load(cc + 1, buf ^ 1);

        const uint32_t bb = sbase + (uint32_t)buf * (PBUFW * 4);
        const uint32_t aHi = bb + aOff, aLo = bb + (uint32_t)(PA_LO * 4) + aOff;
        const uint32_t bHi = bb + (uint32_t)(PB_HI * 4) + bOff;
        const uint32_t bLo = bb + (uint32_t)(PB_LO * 4) + bOff;
#pragma unroll
        for (int ksub = 0; ksub < 2; ksub++) {
            const uint32_t k0 = (uint32_t)(ksub * 8 * 4);
            uint32_t ahi[2][4], alo[2][4];
            ldsm4(ahi[0], aHi + k0);
            ldsm4(ahi[1], aHi + k0 + 16 * PASTR * 4);
            ldsm4(alo[0], aLo + k0);
            ldsm4(alo[1], aLo + k0 + 16 * PASTR * 4);
            uint32_t bhi[4][2], blo[4][2];
            {
                uint32_t t4[4];
                ldsm4(t4, bHi + k0);
                bhi[0][0] = t4[0]; bhi[0][1] = t4[1]; bhi[1][0] = t4[2]; bhi[1][1] = t4[3];
                ldsm4(t4, bHi + k0 + 16 * PASTR * 4);
                bhi[2][0] = t4[0]; bhi[2][1] = t4[1]; bhi[3][0] = t4[2]; bhi[3][1] = t4[3];
                ldsm4(t4, bLo + k0);
                blo[0][0] = t4[0]; blo[0][1] = t4[1]; blo[1][0] = t4[2]; blo[1][1] = t4[3];
                ldsm4(t4, bLo + k0 + 16 * PASTR * 4);
                blo[2][0] = t4[0]; blo[2][1] = t4[1]; blo[3][0] = t4[2]; blo[3][1] = t4[3];
            }
#pragma unroll
            for (int mt = 0; mt < 2; mt++)
#pragma unroll
                for (int nt = 0; nt < 4; nt++) {
                    MMAH(D[mt][nt], ahi[mt], bhi[nt]);
                    MMAH(E[mt][nt], ahi[mt], blo[nt]);
                    MMAH(E[mt][nt], alo[mt], bhi[nt]);
                }
        }
    }

#pragma unroll
    for (int mt = 0; mt < 2; mt++)
#pragma unroll
        for (int nt = 0; nt < 4; nt++) {
            int r0 = mBase + warpM + mt * 16 + gid;
            int n0 = nBase + warpN + nt * 8 + 2 * tig;
            float v0 = D[mt][nt][0] + E[mt][nt][0] * 0.0009765625f;
            float v1 = D[mt][nt][1] + E[mt][nt][1] * 0.0009765625f;
            float v2 = D[mt][nt][2] + E[mt][nt][2] * 0.0009765625f;
            float v3 = D[mt][nt][3] + E[mt][nt][3] * 0.0009765625f;
            if (r0 < NED + 1) {
                g_P[(size_t)r0 * G4D + n0]     = v0;
                g_P[(size_t)r0 * G4D + n0 + 1] = v1;
            }
            if (r0 + 8 < NED + 1) {
                g_P[(size_t)(r0+8) * G4D + n0]   = v2;
                g_P[(size_t)(r0+8) * G4D + n0+1] = v3;
            }
        }
}

// ---------------------------------------------------------------------------
// K-rnn: persistent recurrence (EXACT round-13/11 reduce: 3-sync chain)
// ---------------------------------------------------------------------------
#define BSTR 260
#define BW_LO 16640
#define AW0   33280
#define AKG   10240
#define ABUF  5120
#define A_LOW 2560
#define ASTR  20
#define PK_SMEM (53760 * 4)

__global__ void __launch_bounds__(512, 1) k_rnn(const int* __restrict__ inputs,
                                                const int* __restrict__ dirs) {
    extern __shared__ float sm[];
    uint32_t* smw = (uint32_t*)sm;
    const uint32_t sbase = smem_u32(sm);
    const int tid = threadIdx.x;
    const int lane = tid & 31, wid = tid >> 5;
    const int kg = wid >> 3, wid8 = wid & 7;
    const int lt = tid & 255;
    const int grp = blockIdx.x;
    const int jt = blockIdx.y;
    const int bBase = blockIdx.x * 128;
    const int jBase = blockIdx.y * 16;
    const int warpM = (wid8 >> 1) * 32, warpN = (wid8 & 1) * 32;

    for (int i = tid; i < 64 * 64; i += 512) {
        int r = i >> 6, q = i & 63;
        int g = r & 3, jl = r >> 2;
        size_t src = ((size_t)(g * HD + jBase + jl)) * HD + q * 8;
        uint4 vh = *(const uint4*)(g_whh_fhi + src);
        uint4 vl = *(const uint4*)(g_whh_flo + src);
        *(uint4*)(smw + r * BSTR + q * 4) = vh;
        *(uint4*)(smw + BW_LO + r * BSTR + q * 4) = vl;
    }
    __syncthreads();

    const uint32_t aOffL = (uint32_t)(((warpM + (lane & 7) + ((lane >> 3) & 1) * 8) * ASTR
                                      + (lane >> 4) * 4) * 4);
    const uint32_t bOffL = (uint32_t)(((warpN + (lane & 7) + ((lane >> 4) & 1) * 8) * BSTR
                                      + ((lane >> 3) & 1) * 4) * 4);
    const uint32_t bHiL = sbase + bOffL;
    const uint32_t bLoL = sbase + (uint32_t)(BW_LO * 4) + bOffL;

    const int bl_ep = tid >> 2;
    const int b_ep = bBase + bl_ep;
    const int j0 = (tid & 3) * 4;
    float cst[4] = {0.f, 0.f, 0.f, 0.f};

    for (int s = 0; s < SD; s++) {
        const int inp = inputs[b_ep * SD + s];
        const int dr  = dirs[b_ep * SD + s];
        float gb[16];
#pragma unroll
        for (int g = 0; g < 4; g++) {
            float4 pv = *(const float4*)(g_P + (size_t)inp * G4D + g * HD + jBase + j0);
            float4 qv = *(const float4*)(g_Q + (size_t)dr * G4D + g * HD + jBase + j0);
            gb[g * 4 + 0] = pv.x + qv.x;
            gb[g * 4 + 1] = pv.y + qv.y;
            gb[g * 4 + 2] = pv.z + qv.z;
            gb[g * 4 + 3] = pv.w + qv.w;
        }

        float D[2][4][4], E[2][4][4];
#pragma unroll
        for (int mt = 0; mt < 2; mt++)
#pragma unroll
            for (int nt = 0; nt < 4; nt++)
#pragma unroll
                for (int r = 0; r < 4; r++) { D[mt][nt][r] = 0.f; E[mt][nt][r] = 0.f; }

        if (s > 0) {
            const __half* __restrict__ hh = g_hh[s & 1];
            const __half* __restrict__ hl = g_hl[s & 1];
            auto load_chunk = [&](int cc, int buf) {
                const int kb = kg * 256 + cc * 32;
                const uint32_t bu = sbase + (uint32_t)((AW0 + kg * AKG + buf * ABUF) * 4);
#pragma unroll
                for (int t = 0; t < 4; t++) {
                    int id = lt + t * 256;
                    int isLo = id >> 9;
                    int rem = id & 511;
                    int r = rem >> 2, t4 = rem & 3;
                    const __half* src = (isLo ? hl : hh) + (size_t)(bBase + r) * HD + kb + t4 * 8;
                    uint32_t dst = bu + (uint32_t)(((isLo ? A_LOW : 0) + r * ASTR + t4 * 4) * 4);
                    cp16(dst, src);
                }
                CP_COMMIT();
            };

            load_chunk(0, 0);
#pragma unroll 1
            for (int cc = 0; cc < 8; cc++) {
                const int buf = cc & 1;
                BARN(1 + kg, 256);
                if (cc < 7) {
                    load_chunk(cc + 1, buf ^ 1);
                    CP_WAIT1();
                } else {
                    CP_WAIT0();
                }
                BARN(3 + kg, 256);

                const uint32_t aHiBase = sbase + (uint32_t)((AW0 + kg * AKG + buf * ABUF) * 4) + aOffL;
                const uint32_t aLoBase = aHiBase + (uint32_t)(A_LOW * 4);
                const int kwBase = kg * 128 + cc * 16;
#pragma unroll
                for (int ksub = 0; ksub < 2; ksub++) {
                    const int k0 = ksub * 8;
                    uint32_t ahi[2][4], alo[2][4];
                    ldsm4(ahi[0], aHiBase + k0 * 4);
                    ldsm4(ahi[1], aHiBase + k0 * 4 + 16 * ASTR * 4);
                    ldsm4(alo[0], aLoBase + k0 * 4);
                    ldsm4(alo[1], aLoBase + k0 * 4 + 16 * ASTR * 4);
                    uint32_t bhi[4][2], blo[4][2];
                    {
                        const uint32_t kwb = (uint32_t)((kwBase + k0) * 4);
                        uint32_t t4[4];
                        ldsm4(t4, bHiL + kwb);
                        bhi[0][0] = t4[0]; bhi[0][1] = t4[1]; bhi[1][0] = t4[2]; bhi[1][1] = t4[3];
                        ldsm4(t4, bHiL + kwb + 16 * BSTR * 4);
                        bhi[2][0] = t4[0]; bhi[2][1] = t4[1]; bhi[3][0] = t4[2]; bhi[3][1] = t4[3];
                        ldsm4(t4, bLoL + kwb);
                        blo[0][0] = t4[0]; blo[0][1] = t4[1]; blo[1][0] = t4[2]; blo[1][1] = t4[3];
                        ldsm4(t4, bLoL + kwb + 16 * BSTR * 4);
                        blo[2][0] = t4[0]; blo[2][1] = t4[1]; blo[3][0] = t4[2]; blo[3][1] = t4[3];
                    }
#pragma unroll
                    for (int mt = 0; mt < 2; mt++)
#pragma unroll
                        for (int nt = 0; nt < 4; nt++) {
                            MMAH(D[mt][nt], ahi[mt], bhi[nt]);
                            MMAH(E[mt][nt], ahi[mt], blo[nt]);
                            MMAH(E[mt][nt], alo[mt], bhi[nt]);
                        }
                }
            }
#pragma unroll
            for (int mt = 0; mt < 2; mt++)
#pragma unroll
                for (int nt = 0; nt < 4; nt++)
#pragma unroll
                    for (int r = 0; r < 4; r++)
                        D[mt][nt][r] += E[mt][nt][r] * 0.0009765625f;
        }

        __syncthreads();
        float* red = sm + AW0;
        if (s > 0) {
            const int gid = lane >> 2, tig = lane & 3;
            if (kg == 1) {
#pragma unroll
                for (int mt = 0; mt < 2; mt++)
#pragma unroll
                    for (int nt = 0; nt < 4; nt++) {
                        int r0 = warpM + mt * 16 + gid;
                        int n0 = warpN + nt * 8 + 2 * tig;
                        red[r0 * 68 + n0]           = D[mt][nt][0];
                        red[r0 * 68 + n0 + 1]       = D[mt][nt][1];
                        red[(r0 + 8) * 68 + n0]     = D[mt][nt][2];
                        red[(r0 + 8) * 68 + n0 + 1] = D[mt][nt][3];
                    }
            }
            __syncthreads();
            if (kg == 0) {
#pragma unroll
                for (int mt = 0; mt < 2; mt++)
#pragma unroll
                    for (int nt = 0; nt < 4; nt++) {
                        int r0 = warpM + mt * 16 + gid;
                        int n0 = warpN + nt * 8 + 2 * tig;
                        red[r0 * 68 + n0]           += D[mt][nt][0];
                        red[r0 * 68 + n0 + 1]       += D[mt][nt][1];
                        red[(r0 + 8) * 68 + n0]     += D[mt][nt][2];
                        red[(r0 + 8) * 68 + n0 + 1] += D[mt][nt][3];
                    }
            }
            __syncthreads();
        }

        // ---- fused LSTM epilogue ----
        {
            __half hhi[4], hlo[4];
            float hf[4];
#pragma unroll
            for (int jj = 0; jj < 4; jj++) {
                float gi = gb[0 * 4 + jj];
                float gf = gb[1 * 4 + jj];
                float gg = gb[2 * 4 + jj];
                float go = gb[3 * 4 + jj];
                if (s > 0) {
                    int nb = (j0 + jj) * 4;
                    gi += red[bl_ep * 68 + nb + 0];
                    gf += red[bl_ep * 68 + nb + 1];
                    gg += red[bl_ep * 68 + nb + 2];
                    go += red[bl_ep * 68 + nb + 3];
                }
                float cn = sigmf(gf) * cst[jj] + sigmf(gi) * tanhf(gg);
                cst[jj] = cn;
                float h = sigmf(go) * tanhf(cn);
                hf[jj] = h;
                h16_split(h, hhi[jj], hlo[jj]);
            }
            __half* hho = g_hh[(s + 1) & 1];
            __half* hlo_ = g_hl[(s + 1) & 1];
            size_t off = (size_t)b_ep * HD + jBase + j0;
            *(__half2*)(hho + off)     = __halves2half2(hhi[0], hhi[1]);
            *(__half2*)(hho + off + 2) = __halves2half2(hhi[2], hhi[3]);
            *(__half2*)(hlo_ + off)     = __halves2half2(hlo[0], hlo[1]);
            *(__half2*)(hlo_ + off + 2) = __halves2half2(hlo[2], hlo[3]);
            if (s == SD - 1)
                *(float4*)(g_hfp + off) = make_float4(hf[0], hf[1], hf[2], hf[3]);
        }

        // ---- flag-vector barrier over this b-group (32 CTAs) ----
        __threadfence();
        __syncthreads();
        if (tid == 0) g_flag[(grp * 32 + jt) * 32] = (unsigned)(s + 1);
        if (tid < 32) {
            while (g_flag[(grp * 32 + tid) * 32] < (unsigned)(s + 1)) { }
        }
        __threadfence();
        __syncthreads();
    }
}

// ---------------------------------------------------------------------------
// MLP layers (fp32)
// ---------------------------------------------------------------------------
__global__ void k_mlp(int which, const float* __restrict__ W, const float* __restrict__ bias) {
    __shared__ float sa[32][33];
    __shared__ float swm[32][33];
    const int tid = threadIdx.x;
    const int tx = tid & 15, ty = tid >> 4;
    const int mBase = blockIdx.x * 32;
    const int nBase = blockIdx.y * 32;
    const float* __restrict__ A = (which == 0) ? g_hfp : g_z1;
    float* __restrict__ out = (which == 0) ? g_z1 : g_z2;

    float acc[4] = {0.f, 0.f, 0.f, 0.f};
    for (int kb = 0; kb < HD; kb += 32) {
#pragma unroll
        for (int i = 0; i < 4; i++) {
            int idx = tid + i * 256;
            int r = idx >> 5, c = idx & 31;
            sa[r][c]  = A[(mBase + r) * HD + kb + c];
            swm[r][c] = W[(nBase + r) * HD + kb + c];
        }
        __syncthreads();
#pragma unroll
        for (int kk = 0; kk < 32; kk++) {
            float a0 = sa[ty][kk], a1 = sa[ty + 16][kk];
            float w0 = swm[tx][kk], w1 = swm[tx + 16][kk];
            acc[0] += a0 * w0; acc[1] += a0 * w1;
            acc[2] += a1 * w0; acc[3] += a1 * w1;
        }
        __syncthreads();
    }
#pragma unroll
    for (int bi = 0; bi < 2; bi++)
#pragma unroll
        for (int ni = 0; ni < 2; ni++) {
            int m = mBase + ty + bi * 16;
            int n = nBase + tx + ni * 16;
            float v = acc[bi * 2 + ni] + bias[n];
            out[m * HD + n] = fmaxf(v, 0.0f);
        }
}

__global__ void k_logits(const float* __restrict__ W3, const float* __restrict__ b3) {
    int idx = blockIdx.x * blockDim.x + threadIdx.x;
    if (idx >= BD * NDD) return;
    int b = idx >> 3, n = idx & 7;
    const float4* z = (const float4*)(g_z2 + b * HD);
    const float4* w = (const float4*)(W3 + n * HD);
    float acc = b3[n];
#pragma unroll 4
    for (int k = 0; k < HD / 4; k++) {
        float4 zv = z[k], wv = w[k];
        acc += zv.x * wv.x + zv.y * wv.y + zv.z * wv.z + zv.w * wv.w;
    }
    g_logits[idx] = acc;
}

// ---------------------------------------------------------------------------
// Head: softmax/top2/loss/dc + query build (fp16 split) + pred_d copy
// ---------------------------------------------------------------------------
__global__ void k_head(const int* __restrict__ inputs, const int* __restrict__ goal,
                       const int* __restrict__ locd, const float* __restrict__ link,
                       const float* __restrict__ dire, const float* __restrict__ pdr,
                       float* __restrict__ out) {
    int b = threadIdx.x;
    float p[NDD];
    float mx = -1e30f;
#pragma unroll
    for (int n = 0; n < NDD; n++) { p[n] = g_logits[b * NDD + n]; mx = fmaxf(mx, p[n]); }
    float se = 0.0f;
#pragma unroll
    for (int n = 0; n < NDD; n++) se += expf(p[n] - mx);
    float lse = mx + logf(se);
#pragma unroll
    for (int n = 0; n < NDD; n++) p[n] -= lse;

    float mx2 = -1e30f;
#pragma unroll
    for (int n = 0; n < NDD; n++) mx2 = fmaxf(mx2, p[n]);
    float se2 = 0.0f;
#pragma unroll
    for (int n = 0; n < NDD; n++) se2 += expf(p[n] - mx2);
    float lse2 = mx2 + logf(se2);

    int i0 = 0; float v0 = p[0];
#pragma unroll
    for (int n = 1; n < NDD; n++) if (p[n] > v0) { v0 = p[n]; i0 = n; }
    int i1 = -1; float v1 = -1e30f;
#pragma unroll
    for (int n = 0; n < NDD; n++) if (n != i0 && p[n] > v1) { v1 = p[n]; i1 = n; }

    int last = inputs[b * SD + SD - 1];
    int lbl = locd[(size_t)(last - 1) * NED + goal[b]];
    float lossi = -(p[lbl] - lse2);
    int corr = (i0 == lbl) || (i1 == lbl);

    const float* le = link + (size_t)last * EDD;
    const float* d0 = dire + (i0 + 1) * DDD;
    const float* d1 = dire + (i1 + 1) * DDD;
#pragma unroll 4
    for (int k = 0; k < EDD; k++) {
        float q = le[k];
        if (k < DDD) q += 0.5f * (d0[k] + d1[k]);
        __half hi, lo; h16_split(q, hi, lo);
        g_qhi[b * EDD + k] = hi;
        g_qlo[b * EDD + k] = lo;
    }

    __shared__ float sl[BD];
    __shared__ int sc[BD];
    sl[b] = lossi; sc[b] = corr;
    __syncthreads();
    for (int st = BD / 2; st > 0; st >>= 1) {
        if (b < st) { sl[b] += sl[b + st]; sc[b] += sc[b + st]; }
        __syncthreads();
    }
    if (b == 0) {
        out[OUT_LOSS] = sl[0] * (5.0f / (float)BD);
        out[OUT_DC] = (float)sc[0];
    }
    for (int i = b; i < BD * NDD * PLD; i += BD) out[OUT_PRED_D + i] = pdr[i];
}

// ---------------------------------------------------------------------------
// Sim GEMM (fp16 2-term): sim = query @ link[1:]^T, tiled x5 into pred_hard.
// ---------------------------------------------------------------------------
__global__ void __launch_bounds__(256, 1) k_sim(float* __restrict__ out) {
    extern __shared__ float psm[];
    const uint32_t sbase = smem_u32(psm);
    const int tid = threadIdx.x;
    const int lane = tid & 31, wid = tid >> 5;
    const int gid = lane >> 2, tig = lane & 3;
    const int mBase = blockIdx.x * 128, nBase = blockIdx.y * 64;
    const int warpM = (wid >> 1) * 32, warpN = (wid & 1) * 32;

    const uint32_t aOff = (uint32_t)(((warpM + (lane & 7) + ((lane >> 3) & 1) * 8) * PASTR
                                     + (lane >> 4) * 4) * 4);
    const uint32_t bOff = (uint32_t)(((warpN + (lane & 7) + ((lane >> 4) & 1) * 8) * PASTR
                                     + ((lane >> 3) & 1) * 4) * 4);

    float D[2][4][4], E[2][4][4];
#pragma unroll
    for (int mt = 0; mt < 2; mt++)
#pragma unroll
        for (int nt = 0; nt < 4; nt++)
#pragma unroll
            for (int r = 0; r < 4; r++) { D[mt][nt][r] = 0.f; E[mt][nt][r] = 0.f; }

    auto load = [&](int cc, int buf) {
        const int kb = cc * 32;
        const uint32_t bu = sbase + (uint32_t)buf * (PBUFW * 4);
#pragma unroll
        for (int t = 0; t < 6; t++) {
            int id = tid + t * 256;
            const __half* src;
            uint32_t dst;
            if (id < 1024) {
                int isLo = id >> 9, rem = id & 511;
                int r = rem >> 2, t4 = rem & 3;
                src = (isLo ? g_qlo : g_qhi) + (size_t)(mBase + r) * EDD + kb + t4 * 8;
                dst = bu + (uint32_t)(((isLo ? PA_LO : 0) + r * PASTR + t4 * 4) * 4);
            } else {
                int id2 = id - 1024;
                int isLo = id2 >> 8, rem = id2 & 255;
                int r = rem >> 2, t4 = rem & 3;
                src = (isLo ? g_link_flo : g_link_fhi) + (size_t)(nBase + r + 1) * EDD + kb + t4 * 8;
                dst = bu + (uint32_t)(((isLo ? PB_LO : PB_HI) + r * PASTR + t4 * 4) * 4);
            }
            cp16(dst, src);
        }
        CP_COMMIT();
    };

    load(0, 0);
#pragma unroll 1
    for (int cc = 0; cc < 4; cc++) {
        const int buf = cc & 1;
        CP_WAIT0();
        __syncthreads();
        if (cc < 3) load(cc + 1, buf ^ 1);

        const uint32_t bb = sbase + (uint32_t)buf * (PBUFW * 4);
        const uint32_t aHi = bb + aOff, aLo = bb + (uint32_t)(PA_LO * 4) + aOff;
        const uint32_t bHi = bb + (uint32_t)(PB_HI * 4) + bOff;
        const uint32_t bLo = bb + (uint32_t)(PB_LO * 4) + bOff;
#pragma unroll
        for (int ksub = 0; ksub < 2; ksub++) {
            const uint32_t k0 = (uint32_t)(ksub * 8 * 4);
            uint32_t ahi[2][4], alo[2][4];
            ldsm4(ahi[0], aHi + k0);
            ldsm4(ahi[1], aHi + k0 + 16 * PASTR * 4);
            ldsm4(alo[0], aLo + k0);
            ldsm4(alo[1], aLo + k0 + 16 * PASTR * 4);
            uint32_t bhi[4][2], blo[4][2];
            {
                uint32_t t4[4];
                ldsm4(t4, bHi + k0);
                bhi[0][0] = t4[0]; bhi[0][1] = t4[1]; bhi[1][0] = t4[2]; bhi[1][1] = t4[3];
                ldsm4(t4, bHi + k0 + 16 * PASTR * 4);
                bhi[2][0] = t4[0]; bhi[2][1] = t4[1]; bhi[3][0] = t4[2]; bhi[3][1] = t4[3];
                ldsm4(t4, bLo + k0);
                blo[0][0] = t4[0]; blo[0][1] = t4[1]; blo[1][0] = t4[2]; blo[1][1] = t4[3];
                ldsm4(t4, bLo + k0 + 16 * PASTR * 4);
                blo[2][0] = t4[0]; blo[2][1] = t4[1]; blo[3][0] = t4[2]; blo[3][1] = t4[3];
            }
#pragma unroll
            for (int mt = 0; mt < 2; mt++)
#pragma unroll
                for (int nt = 0; nt < 4; nt++) {
                    MMAH(D[mt][nt], ahi[mt], bhi[nt]);
                    MMAH(E[mt][nt], ahi[mt], blo[nt]);
                    MMAH(E[mt][nt], alo[mt], bhi[nt]);
                }
        }
    }

#pragma unroll
    for (int mt = 0; mt < 2; mt++)
#pragma unroll
        for (int nt = 0; nt < 4; nt++) {
            int r0 = mBase + warpM + mt * 16 + gid;
            int n0 = nBase + warpN + nt * 8 + 2 * tig;
            float2 va = make_float2(D[mt][nt][0] + E[mt][nt][0] * 0.0009765625f,
                                    D[mt][nt][1] + E[mt][nt][1] * 0.0009765625f);
            float2 vb = make_float2(D[mt][nt][2] + E[mt][nt][2] * 0.0009765625f,
                                    D[mt][nt][3] + E[mt][nt][3] * 0.0009765625f);
            size_t basea = (size_t)r0 * (NED * PLD) + n0;
            size_t baseb = (size_t)(r0 + 8) * (NED * PLD) + n0;
#pragma unroll
            for (int pl = 0; pl < PLD; pl++) {
                *(float2*)(out + basea + (size_t)pl * NED) = va;
                *(float2*)(out + baseb + (size_t)pl * NED) = vb;
            }
        }
}

// ---------------------------------------------------------------------------
// Launcher
// ---------------------------------------------------------------------------
extern "C" void kernel_launch(void* const* d_in, const int* in_sizes, int n_in,
                              void* d_out, int out_size) {
    const int*   inputs = (const int*)d_in[0];
    const int*   dirs   = (const int*)d_in[1];
    const int*   goal   = (const int*)d_in[2];
    const int*   locd   = (const int*)d_in[3];
    const float* pdr    = (const float*)d_in[4];
    const float* link   = (const float*)d_in[5];
    const float* dire   = (const float*)d_in[6];
    const float* w_ih   = (const float*)d_in[7];
    const float* b_ih   = (const float*)d_in[8];
    const float* w_hh   = (const float*)d_in[9];
    const float* b_hh   = (const float*)d_in[10];
    const float* W1     = (const float*)d_in[11];
    const float* b1     = (const float*)d_in[12];
    const float* W2     = (const float*)d_in[13];
    const float* b2     = (const float*)d_in[14];
    const float* W3     = (const float*)d_in[15];
    const float* b3     = (const float*)d_in[16];
    float* out = (float*)d_out;

    static int smem_set = 0;
    if (!smem_set) {
        cudaFuncSetAttribute(k_rnn, cudaFuncAttributeMaxDynamicSharedMemorySize, PK_SMEM);
        cudaFuncSetAttribute(k_pe, cudaFuncAttributeMaxDynamicSharedMemorySize, PE_SMEM);
        cudaFuncSetAttribute(k_sim, cudaFuncAttributeMaxDynamicSharedMemorySize, PE_SMEM);
        smem_set = 1;
    }

    k_init<<<16, 256>>>();
    k_split<<<512, 256>>>(w_hh, w_ih, link);
    k_q<<<((NDD+1) * G4D + 255) / 256, 256>>>(dire, w_ih, b_ih, b_hh);

    // P = link_emb @ Wih_link^T (fp16 2-term)
    k_pe<<<dim3(65, 32), 256, PE_SMEM>>>();

    // Persistent recurrence (round-13 reduce structure)
    k_rnn<<<dim3(4, 32), 512, PK_SMEM>>>(inputs, dirs);

    k_mlp<<<dim3(BD / 32, HD / 32), 256>>>(0, W1, b1);
    k_mlp<<<dim3(BD / 32, HD / 32), 256>>>(1, W2, b2);
    k_logits<<<(BD * NDD + 255) / 256, 256>>>(W3, b3);
    k_head<<<1, BD>>>(inputs, goal, locd, link, dire, pdr, out);

    // Sim GEMM (fp16 2-term) + 5x tiling
    k_sim<<<dim3(4, 128), 256, PE_SMEM>>>(out);
}

// round 16
// speedup vs baseline: 1.0530x; 1.0401x over previous
#include <cuda_runtime.h>
#include <cuda_fp16.h>
#include <math.h>
#include <stdint.h>

// Problem dims
#define BD   512
#define SD   128
#define NED  8192
#define EDD  128
#define DDD  32
#define IND  160
#define HD   512
#define G4D  2048
#define NDD  8
#define PLD  5

#define OUT_PRED_D (512u*8192u*5u)
#define OUT_LOSS   (OUT_PRED_D + 512u*8u*5u)
#define OUT_DC     (OUT_LOSS + 1u)

// ---------------- device scratch ----------------
__device__ float g_P[(NED+1)*G4D];
__device__ float g_Q[(NDD+1)*G4D];
__device__ __half g_whh_fhi[G4D*HD], g_whh_flo[G4D*HD];
__device__ __half g_hh[2][BD*HD], g_hl[2][BD*HD];
__device__ __half g_link_fhi[(NED+1)*EDD], g_link_flo[(NED+1)*EDD];
__device__ __half g_wih_fhi[G4D*EDD], g_wih_flo[G4D*EDD];
__device__ float g_hfp[BD*HD];
__device__ float g_z1[BD*HD], g_z2[BD*HD];
__device__ float g_logits[BD*NDD], g_query[BD*EDD];
__device__ volatile unsigned g_flag[4 * 32 * 32];

__device__ __forceinline__ float sigmf(float x) { return 1.0f / (1.0f + expf(-x)); }

__device__ __forceinline__ void h16_split(float v, __half& hi, __half& lo) {
    hi = __float2half_rn(v);
    float r = v - __half2float(hi);
    lo = __float2half_rn(r * 1024.0f);
}

__device__ __forceinline__ uint32_t smem_u32(const void* p) {
    uint32_t a;
    asm("{ .reg .u64 t; cvta.to.shared.u64 t, %1; cvt.u32.u64 %0, t; }" : "=r"(a) : "l"(p));
    return a;
}
__device__ __forceinline__ void cp16(uint32_t dst, const void* src) {
    asm volatile("cp.async.cg.shared.global [%0], [%1], 16;" :: "r"(dst), "l"(src));
}
__device__ __forceinline__ void ldsm4(uint32_t* r, uint32_t addr) {
    asm volatile("ldmatrix.sync.aligned.m8n8.x4.shared.b16 {%0,%1,%2,%3}, [%4];"
                 : "=r"(r[0]), "=r"(r[1]), "=r"(r[2]), "=r"(r[3]) : "r"(addr));
}
#define CP_COMMIT() asm volatile("cp.async.commit_group;" ::: "memory")
#define CP_WAIT0()  asm volatile("cp.async.wait_group 0;" ::: "memory")
#define CP_WAIT1()  asm volatile("cp.async.wait_group 1;" ::: "memory")
#define BARN(id, n) asm volatile("bar.sync %0, %1;" :: "r"(id), "r"(n) : "memory")

#define MMAH(d, a, b) \
    asm volatile("mma.sync.aligned.m16n8k16.row.col.f32.f16.f16.f32 " \
                 "{%0,%1,%2,%3},{%4,%5,%6,%7},{%8,%9},{%0,%1,%2,%3};" \
                 : "+f"(d[0]), "+f"(d[1]), "+f"(d[2]), "+f"(d[3]) \
                 : "r"(a[0]), "r"(a[1]), "r"(a[2]), "r"(a[3]), "r"(b[0]), "r"(b[1]))

// ---------------------------------------------------------------------------
// K-prep: fused flag init + fp16 splits + Q build (one launch)
// ---------------------------------------------------------------------------
__global__ void k_prep(const float* __restrict__ whh, const float* __restrict__ wih,
                       const float* __restrict__ link, const float* __restrict__ dire,
                       const float* __restrict__ bih, const float* __restrict__ bhh) {
    int i = blockIdx.x * blockDim.x + threadIdx.x;
    int stride = gridDim.x * blockDim.x;
    if (i < 4 * 32 * 32) g_flag[i] = 0u;
    for (int idx = i; idx < G4D*HD; idx += stride) {
        __half hi, lo; h16_split(whh[idx], hi, lo);
        g_whh_fhi[idx] = hi; g_whh_flo[idx] = lo;
    }
    for (int idx = i; idx < G4D*EDD; idx += stride) {
        int n = idx >> 7, k = idx & 127;
        __half hi, lo; h16_split(wih[n * IND + k], hi, lo);
        g_wih_fhi[idx] = hi; g_wih_flo[idx] = lo;
    }
    for (int idx = i; idx < (NED+1)*EDD; idx += stride) {
        __half hi, lo; h16_split(link[idx], hi, lo);
        g_link_fhi[idx] = hi; g_link_flo[idx] = lo;
    }
    for (int idx = i; idx < (NDD+1) * G4D; idx += stride) {
        int d = idx / G4D, n = idx - d * G4D;
        float acc = bih[n] + bhh[n];
#pragma unroll 8
        for (int k = 0; k < DDD; k++) acc += dire[d * DDD + k] * wih[n * IND + EDD + k];
        g_Q[idx] = acc;
    }
}

// ---------------------------------------------------------------------------
// K-pe (fp16 2-term, 512 threads / 16 warps, warp tile 32x16):
//   P = link_emb @ Wih_link^T. M=8193, N=2048, K=128. CTA 128m x 64n.
// ---------------------------------------------------------------------------
#define PASTR 20
#define PA_LO 2560
#define PB_HI 5120
#define PB_LO 6400
#define PBUFW 7680
#define PE_SMEM (2 * PBUFW * 4)

__global__ void __launch_bounds__(512) k_pe() {
    extern __shared__ float psm[];
    const uint32_t sbase = smem_u32(psm);
    const int tid = threadIdx.x;
    const int lane = tid & 31, wid = tid >> 5;
    const int gid = lane >> 2, tig = lane & 3;
    const int mBase = blockIdx.x * 128, nBase = blockIdx.y * 64;
    const int warpM = (wid >> 2) * 32, warpN = (wid & 3) * 16;

    const uint32_t aOff = (uint32_t)(((warpM + (lane & 7) + ((lane >> 3) & 1) * 8) * PASTR
                                     + (lane >> 4) * 4) * 4);
    const uint32_t bOff = (uint32_t)(((warpN + (lane & 7) + ((lane >> 4) & 1) * 8) * PASTR
                                     + ((lane >> 3) & 1) * 4) * 4);

    float D[2][2][4], E[2][2][4];
#pragma unroll
    for (int mt = 0; mt < 2; mt++)
#pragma unroll
        for (int nt = 0; nt < 2; nt++)
#pragma unroll
            for (int r = 0; r < 4; r++) { D[mt][nt][r] = 0.f; E[mt][nt][r] = 0.f; }

    auto load = [&](int cc, int buf) {
        const int kb = cc * 32;
        const uint32_t bu = sbase + (uint32_t)buf * (PBUFW * 4);
#pragma unroll
        for (int t = 0; t < 3; t++) {
            int id = tid + t * 512;
            const __half* src;
            uint32_t dst;
            if (id < 1024) {
                int isLo = id >> 9, rem = id & 511;
                int r = rem >> 2, t4 = rem & 3;
                int rg = mBase + r; if (rg > NED) rg = NED;
                src = (isLo ? g_link_flo : g_link_fhi) + (size_t)rg * EDD + kb + t4 * 8;
                dst = bu + (uint32_t)(((isLo ? PA_LO : 0) + r * PASTR + t4 * 4) * 4);
            } else {
                int id2 = id - 1024;
                int isLo = id2 >> 8, rem = id2 & 255;
                int r = rem >> 2, t4 = rem & 3;
                src = (isLo ? g_wih_flo : g_wih_fhi) + (size_t)(nBase + r) * EDD + kb + t4 * 8;
                dst = bu + (uint32_t)(((isLo ? PB_LO : PB_HI) + r * PASTR + t4 * 4) * 4);
            }
            cp16(dst, src);
        }
        CP_COMMIT();
    };

    load(0, 0);
#pragma unroll 1
    for (int cc = 0; cc < 4; cc++) {
        const int buf = cc & 1;
        CP_WAIT0();
        __syncthreads();
        if (cc < 3) load(cc + 1, buf ^ 1);

        const uint32_t bb = sbase + (uint32_t)buf * (PBUFW * 4);
        const uint32_t aHi = bb + aOff, aLo = bb + (uint32_t)(PA_LO * 4) + aOff;
        const uint32_t bHi = bb + (uint32_t)(PB_HI * 4) + bOff;
        const uint32_t bLo = bb + (uint32_t)(PB_LO * 4) + bOff;
#pragma unroll
        for (int ksub = 0; ksub < 2; ksub++) {
            const uint32_t k0 = (uint32_t)(ksub * 8 * 4);
            uint32_t ahi[2][4], alo[2][4];
            ldsm4(ahi[0], aHi + k0);
            ldsm4(ahi[1], aHi + k0 + 16 * PASTR * 4);
            ldsm4(alo[0], aLo + k0);
            ldsm4(alo[1], aLo + k0 + 16 * PASTR * 4);
            uint32_t bhi[2][2], blo[2][2];
            {
                uint32_t t4[4];
                ldsm4(t4, bHi + k0);
                bhi[0][0] = t4[0]; bhi[0][1] = t4[1]; bhi[1][0] = t4[2]; bhi[1][1] = t4[3];
                ldsm4(t4, bLo + k0);
                blo[0][0] = t4[0]; blo[0][1] = t4[1]; blo[1][0] = t4[2]; blo[1][1] = t4[3];
            }
#pragma unroll
            for (int mt = 0; mt < 2; mt++)
#pragma unroll
                for (int nt = 0; nt < 2; nt++) {
                    MMAH(D[mt][nt], ahi[mt], bhi[nt]);
                    MMAH(E[mt][nt], ahi[mt], blo[nt]);
                    MMAH(E[mt][nt], alo[mt], bhi[nt]);
                }
        }
    }

#pragma unroll
    for (int mt = 0; mt < 2; mt++)
#pragma unroll
        for (int nt = 0; nt < 2; nt++) {
            int r0 = mBase + warpM + mt * 16 + gid;
            int n0 = nBase + warpN + nt * 8 + 2 * tig;
            float v0 = D[mt][nt][0] + E[mt][nt][0] * 0.0009765625f;
            float v1 = D[mt][nt][1] + E[mt][nt][1] * 0.0009765625f;
            float v2 = D[mt][nt][2] + E[mt][nt][2] * 0.0009765625f;
            float v3 = D[mt][nt][3] + E[mt][nt][3] * 0.0009765625f;
            if (r0 < NED + 1) {
                g_P[(size_t)r0 * G4D + n0]     = v0;
                g_P[(size_t)r0 * G4D + n0 + 1] = v1;
            }
            if (r0 + 8 < NED + 1) {
                g_P[(size_t)(r0+8) * G4D + n0]   = v2;
                g_P[(size_t)(r0+8) * G4D + n0+1] = v3;
            }
        }
}

// ---------------------------------------------------------------------------
// K-rnn: persistent recurrence (EXACT round-13 structure)
// ---------------------------------------------------------------------------
#define BSTR 260
#define BW_LO 16640
#define AW0   33280
#define AKG   10240
#define ABUF  5120
#define A_LOW 2560
#define ASTR  20
#define PK_SMEM (53760 * 4)

__global__ void __launch_bounds__(512, 1) k_rnn(const int* __restrict__ inputs,
                                                const int* __restrict__ dirs) {
    extern __shared__ float sm[];
    uint32_t* smw = (uint32_t*)sm;
    const uint32_t sbase = smem_u32(sm);
    const int tid = threadIdx.x;
    const int lane = tid & 31, wid = tid >> 5;
    const int kg = wid >> 3, wid8 = wid & 7;
    const int lt = tid & 255;
    const int grp = blockIdx.x;
    const int jt = blockIdx.y;
    const int bBase = blockIdx.x * 128;
    const int jBase = blockIdx.y * 16;
    const int warpM = (wid8 >> 1) * 32, warpN = (wid8 & 1) * 32;

    for (int i = tid; i < 64 * 64; i += 512) {
        int r = i >> 6, q = i & 63;
        int g = r & 3, jl = r >> 2;
        size_t src = ((size_t)(g * HD + jBase + jl)) * HD + q * 8;
        uint4 vh = *(const uint4*)(g_whh_fhi + src);
        uint4 vl = *(const uint4*)(g_whh_flo + src);
        *(uint4*)(smw + r * BSTR + q * 4) = vh;
        *(uint4*)(smw + BW_LO + r * BSTR + q * 4) = vl;
    }
    __syncthreads();

    const uint32_t aOffL = (uint32_t)(((warpM + (lane & 7) + ((lane >> 3) & 1) * 8) * ASTR
                                      + (lane >> 4) * 4) * 4);
    const uint32_t bOffL = (uint32_t)(((warpN + (lane & 7) + ((lane >> 4) & 1) * 8) * BSTR
                                      + ((lane >> 3) & 1) * 4) * 4);
    const uint32_t bHiL = sbase + bOffL;
    const uint32_t bLoL = sbase + (uint32_t)(BW_LO * 4) + bOffL;

    const int bl_ep = tid >> 2;
    const int b_ep = bBase + bl_ep;
    const int j0 = (tid & 3) * 4;
    float cst[4] = {0.f, 0.f, 0.f, 0.f};

    for (int s = 0; s < SD; s++) {
        const int inp = inputs[b_ep * SD + s];
        const int dr  = dirs[b_ep * SD + s];
        float gb[16];
#pragma unroll
        for (int g = 0; g < 4; g++) {
            float4 pv = *(const float4*)(g_P + (size_t)inp * G4D + g * HD + jBase + j0);
            float4 qv = *(const float4*)(g_Q + (size_t)dr * G4D + g * HD + jBase + j0);
            gb[g * 4 + 0] = pv.x + qv.x;
            gb[g * 4 + 1] = pv.y + qv.y;
            gb[g * 4 + 2] = pv.z + qv.z;
            gb[g * 4 + 3] = pv.w + qv.w;
        }

        float D[2][4][4], E[2][4][4];
#pragma unroll
        for (int mt = 0; mt < 2; mt++)
#pragma unroll
            for (int nt = 0; nt < 4; nt++)
#pragma unroll
                for (int r = 0; r < 4; r++) { D[mt][nt][r] = 0.f; E[mt][nt][r] = 0.f; }

        if (s > 0) {
            const __half* __restrict__ hh = g_hh[s & 1];
            const __half* __restrict__ hl = g_hl[s & 1];
            auto load_chunk = [&](int cc, int buf) {
                const int kb = kg * 256 + cc * 32;
                const uint32_t bu = sbase + (uint32_t)((AW0 + kg * AKG + buf * ABUF) * 4);
#pragma unroll
                for (int t = 0; t < 4; t++) {
                    int id = lt + t * 256;
                    int isLo = id >> 9;
                    int rem = id & 511;
                    int r = rem >> 2, t4 = rem & 3;
                    const __half* src = (isLo ? hl : hh) + (size_t)(bBase + r) * HD + kb + t4 * 8;
                    uint32_t dst = bu + (uint32_t)(((isLo ? A_LOW : 0) + r * ASTR + t4 * 4) * 4);
                    cp16(dst, src);
                }
                CP_COMMIT();
            };

            load_chunk(0, 0);
#pragma unroll 1
            for (int cc = 0; cc < 8; cc++) {
                const int buf = cc & 1;
                BARN(1 + kg, 256);
                if (cc < 7) {
                    load_chunk(cc + 1, buf ^ 1);
                    CP_WAIT1();
                } else {
                    CP_WAIT0();
                }
                BARN(3 + kg, 256);

                const uint32_t aHiBase = sbase + (uint32_t)((AW0 + kg * AKG + buf * ABUF) * 4) + aOffL;
                const uint32_t aLoBase = aHiBase + (uint32_t)(A_LOW * 4);
                const int kwBase = kg * 128 + cc * 16;
#pragma unroll
                for (int ksub = 0; ksub < 2; ksub++) {
                    const int k0 = ksub * 8;
                    uint32_t ahi[2][4], alo[2][4];
                    ldsm4(ahi[0], aHiBase + k0 * 4);
                    ldsm4(ahi[1], aHiBase + k0 * 4 + 16 * ASTR * 4);
                    ldsm4(alo[0], aLoBase + k0 * 4);
                    ldsm4(alo[1], aLoBase + k0 * 4 + 16 * ASTR * 4);
                    uint32_t bhi[4][2], blo[4][2];
                    {
                        const uint32_t kwb = (uint32_t)((kwBase + k0) * 4);
                        uint32_t t4[4];
                        ldsm4(t4, bHiL + kwb);
                        bhi[0][0] = t4[0]; bhi[0][1] = t4[1]; bhi[1][0] = t4[2]; bhi[1][1] = t4[3];
                        ldsm4(t4, bHiL + kwb + 16 * BSTR * 4);
                        bhi[2][0] = t4[0]; bhi[2][1] = t4[1]; bhi[3][0] = t4[2]; bhi[3][1] = t4[3];
                        ldsm4(t4, bLoL + kwb);
                        blo[0][0] = t4[0]; blo[0][1] = t4[1]; blo[1][0] = t4[2]; blo[1][1] = t4[3];
                        ldsm4(t4, bLoL + kwb + 16 * BSTR * 4);
                        blo[2][0] = t4[0]; blo[2][1] = t4[1]; blo[3][0] = t4[2]; blo[3][1] = t4[3];
                    }
#pragma unroll
                    for (int mt = 0; mt < 2; mt++)
#pragma unroll
                        for (int nt = 0; nt < 4; nt++) {
                            MMAH(D[mt][nt], ahi[mt], bhi[nt]);
                            MMAH(E[mt][nt], ahi[mt], blo[nt]);
                            MMAH(E[mt][nt], alo[mt], bhi[nt]);
                        }
                }
            }
#pragma unroll
            for (int mt = 0; mt < 2; mt++)
#pragma unroll
                for (int nt = 0; nt < 4; nt++)
#pragma unroll
                    for (int r = 0; r < 4; r++)
                        D[mt][nt][r] += E[mt][nt][r] * 0.0009765625f;
        }

        __syncthreads();
        float* red = sm + AW0;
        if (s > 0) {
            const int gid = lane >> 2, tig = lane & 3;
            if (kg == 1) {
#pragma unroll
                for (int mt = 0; mt < 2; mt++)
#pragma unroll
                    for (int nt = 0; nt < 4; nt++) {
                        int r0 = warpM + mt * 16 + gid;
                        int n0 = warpN + nt * 8 + 2 * tig;
                        red[r0 * 68 + n0]           = D[mt][nt][0];
                        red[r0 * 68 + n0 + 1]       = D[mt][nt][1];
                        red[(r0 + 8) * 68 + n0]     = D[mt][nt][2];
                        red[(r0 + 8) * 68 + n0 + 1] = D[mt][nt][3];
                    }
            }
            __syncthreads();
            if (kg == 0) {
#pragma unroll
                for (int mt = 0; mt < 2; mt++)
#pragma unroll
                    for (int nt = 0; nt < 4; nt++) {
                        int r0 = warpM + mt * 16 + gid;
                        int n0 = warpN + nt * 8 + 2 * tig;
                        red[r0 * 68 + n0]           += D[mt][nt][0];
                        red[r0 * 68 + n0 + 1]       += D[mt][nt][1];
                        red[(r0 + 8) * 68 + n0]     += D[mt][nt][2];
                        red[(r0 + 8) * 68 + n0 + 1] += D[mt][nt][3];
                    }
            }
            __syncthreads();
        }

        {
            __half hhi[4], hlo[4];
            float hf[4];
#pragma unroll
            for (int jj = 0; jj < 4; jj++) {
                float gi = gb[0 * 4 + jj];
                float gf = gb[1 * 4 + jj];
                float gg = gb[2 * 4 + jj];
                float go = gb[3 * 4 + jj];
                if (s > 0) {
                    int nb = (j0 + jj) * 4;
                    gi += red[bl_ep * 68 + nb + 0];
                    gf += red[bl_ep * 68 + nb + 1];
                    gg += red[bl_ep * 68 + nb + 2];
                    go += red[bl_ep * 68 + nb + 3];
                }
                float cn = sigmf(gf) * cst[jj] + sigmf(gi) * tanhf(gg);
                cst[jj] = cn;
                float h = sigmf(go) * tanhf(cn);
                hf[jj] = h;
                h16_split(h, hhi[jj], hlo[jj]);
            }
            __half* hho = g_hh[(s + 1) & 1];
            __half* hlo_ = g_hl[(s + 1) & 1];
            size_t off = (size_t)b_ep * HD + jBase + j0;
            *(__half2*)(hho + off)     = __halves2half2(hhi[0], hhi[1]);
            *(__half2*)(hho + off + 2) = __halves2half2(hhi[2], hhi[3]);
            *(__half2*)(hlo_ + off)     = __halves2half2(hlo[0], hlo[1]);
            *(__half2*)(hlo_ + off + 2) = __halves2half2(hlo[2], hlo[3]);
            if (s == SD - 1)
                *(float4*)(g_hfp + off) = make_float4(hf[0], hf[1], hf[2], hf[3]);
        }

        __threadfence();
        __syncthreads();
        if (tid == 0) g_flag[(grp * 32 + jt) * 32] = (unsigned)(s + 1);
        if (tid < 32) {
            while (g_flag[(grp * 32 + tid) * 32] < (unsigned)(s + 1)) { }
        }
        __threadfence();
        __syncthreads();
    }
}

// ---------------------------------------------------------------------------
// MLP layers (fp32)
// ---------------------------------------------------------------------------
__global__ void k_mlp(int which, const float* __restrict__ W, const float* __restrict__ bias) {
    __shared__ float sa[32][33];
    __shared__ float swm[32][33];
    const int tid = threadIdx.x;
    const int tx = tid & 15, ty = tid >> 4;
    const int mBase = blockIdx.x * 32;
    const int nBase = blockIdx.y * 32;
    const float* __restrict__ A = (which == 0) ? g_hfp : g_z1;
    float* __restrict__ out = (which == 0) ? g_z1 : g_z2;

    float acc[4] = {0.f, 0.f, 0.f, 0.f};
    for (int kb = 0; kb < HD; kb += 32) {
#pragma unroll
        for (int i = 0; i < 4; i++) {
            int idx = tid + i * 256;
            int r = idx >> 5, c = idx & 31;
            sa[r][c]  = A[(mBase + r) * HD + kb + c];
            swm[r][c] = W[(nBase + r) * HD + kb + c];
        }
        __syncthreads();
#pragma unroll
        for (int kk = 0; kk < 32; kk++) {
            float a0 = sa[ty][kk], a1 = sa[ty + 16][kk];
            float w0 = swm[tx][kk], w1 = swm[tx + 16][kk];
            acc[0] += a0 * w0; acc[1] += a0 * w1;
            acc[2] += a1 * w0; acc[3] += a1 * w1;
        }
        __syncthreads();
    }
#pragma unroll
    for (int bi = 0; bi < 2; bi++)
#pragma unroll
        for (int ni = 0; ni < 2; ni++) {
            int m = mBase + ty + bi * 16;
            int n = nBase + tx + ni * 16;
            float v = acc[bi * 2 + ni] + bias[n];
            out[m * HD + n] = fmaxf(v, 0.0f);
        }
}

__global__ void k_logits(const float* __restrict__ W3, const float* __restrict__ b3) {
    int idx = blockIdx.x * blockDim.x + threadIdx.x;
    if (idx >= BD * NDD) return;
    int b = idx >> 3, n = idx & 7;
    const float4* z = (const float4*)(g_z2 + b * HD);
    const float4* w = (const float4*)(W3 + n * HD);
    float acc = b3[n];
#pragma unroll 4
    for (int k = 0; k < HD / 4; k++) {
        float4 zv = z[k], wv = w[k];
        acc += zv.x * wv.x + zv.y * wv.y + zv.z * wv.z + zv.w * wv.w;
    }
    g_logits[idx] = acc;
}

// ---------------------------------------------------------------------------
// Head
// ---------------------------------------------------------------------------
__global__ void k_head(const int* __restrict__ inputs, const int* __restrict__ goal,
                       const int* __restrict__ locd, const float* __restrict__ link,
                       const float* __restrict__ dire, const float* __restrict__ pdr,
                       float* __restrict__ out) {
    int b = threadIdx.x;
    float p[NDD];
    float mx = -1e30f;
#pragma unroll
    for (int n = 0; n < NDD; n++) { p[n] = g_logits[b * NDD + n]; mx = fmaxf(mx, p[n]); }
    float se = 0.0f;
#pragma unroll
    for (int n = 0; n < NDD; n++) se += expf(p[n] - mx);
    float lse = mx + logf(se);
#pragma unroll
    for (int n = 0; n < NDD; n++) p[n] -= lse;

    float mx2 = -1e30f;
#pragma unroll
    for (int n = 0; n < NDD; n++) mx2 = fmaxf(mx2, p[n]);
    float se2 = 0.0f;
#pragma unroll
    for (int n = 0; n < NDD; n++) se2 += expf(p[n] - mx2);
    float lse2 = mx2 + logf(se2);

    int i0 = 0; float v0 = p[0];
#pragma unroll
    for (int n = 1; n < NDD; n++) if (p[n] > v0) { v0 = p[n]; i0 = n; }
    int i1 = -1; float v1 = -1e30f;
#pragma unroll
    for (int n = 0; n < NDD; n++) if (n != i0 && p[n] > v1) { v1 = p[n]; i1 = n; }

    int last = inputs[b * SD + SD - 1];
    int lbl = locd[(size_t)(last - 1) * NED + goal[b]];
    float lossi = -(p[lbl] - lse2);
    int corr = (i0 == lbl) || (i1 == lbl);

    const float* le = link + (size_t)last * EDD;
    const float* d0 = dire + (i0 + 1) * DDD;
    const float* d1 = dire + (i1 + 1) * DDD;
#pragma unroll 4
    for (int k = 0; k < EDD; k++) {
        float q = le[k];
        if (k < DDD) q += 0.5f * (d0[k] + d1[k]);
        g_query[b * EDD + k] = q;
    }

    __shared__ float sl[BD];
    __shared__ int sc[BD];
    sl[b] = lossi; sc[b] = corr;
    __syncthreads();
    for (int st = BD / 2; st > 0; st >>= 1) {
        if (b < st) { sl[b] += sl[b + st]; sc[b] += sc[b + st]; }
        __syncthreads();
    }
    if (b == 0) {
        out[OUT_LOSS] = sl[0] * (5.0f / (float)BD);
        out[OUT_DC] = (float)sc[0];
    }
    for (int i = b; i < BD * NDD * PLD; i += BD) out[OUT_PRED_D + i] = pdr[i];
}

// ---------------------------------------------------------------------------
// Sim GEMM (fp32, round-13 version)
// ---------------------------------------------------------------------------
__global__ void k_sim(const float* __restrict__ link, float* __restrict__ out) {
    __shared__ float sq[64][17];
    __shared__ float sl[16][65];
    const int tid = threadIdx.x;
    const int tx = tid & 15, ty = tid >> 4;
    const int eBase = blockIdx.x * 64;
    const int mBase = blockIdx.y * 64;

    float acc[16];
#pragma unroll
    for (int i = 0; i < 16; i++) acc[i] = 0.0f;

    for (int kb = 0; kb < EDD; kb += 16) {
#pragma unroll
        for (int i = 0; i < 4; i++) {
            int idx = tid + i * 256;
            int r = idx >> 4, c = idx & 15;
            sq[r][c] = g_query[(mBase + r) * EDD + kb + c];
            sl[c][r] = link[((size_t)(eBase + r + 1)) * EDD + kb + c];
        }
        __syncthreads();
#pragma unroll
        for (int kk = 0; kk < 16; kk++) {
            float a0 = sq[ty][kk],      a1 = sq[ty + 16][kk];
            float a2 = sq[ty + 32][kk], a3 = sq[ty + 48][kk];
            float w0 = sl[kk][tx],      w1 = sl[kk][tx + 16];
            float w2 = sl[kk][tx + 32], w3 = sl[kk][tx + 48];
            acc[0]  += a0 * w0; acc[1]  += a0 * w1; acc[2]  += a0 * w2; acc[3]  += a0 * w3;
            acc[4]  += a1 * w0; acc[5]  += a1 * w1; acc[6]  += a1 * w2; acc[7]  += a1 * w3;
            acc[8]  += a2 * w0; acc[9]  += a2 * w1; acc[10] += a2 * w2; acc[11] += a2 * w3;
            acc[12] += a3 * w0; acc[13] += a3 * w1; acc[14] += a3 * w2; acc[15] += a3 * w3;
        }
        __syncthreads();
    }
#pragma unroll
    for (int mi = 0; mi < 4; mi++)
#pragma unroll
        for (int ni = 0; ni < 4; ni++) {
            int b = mBase + ty + mi * 16;
            int e = eBase + tx + ni * 16;
            float v = acc[mi * 4 + ni];
            size_t base = (size_t)b * (NED * PLD) + e;
#pragma unroll
            for (int pl = 0; pl < PLD; pl++) out[base + (size_t)pl * NED] = v;
        }
}

// ---------------------------------------------------------------------------
// Launcher
// ---------------------------------------------------------------------------
extern "C" void kernel_launch(void* const* d_in, const int* in_sizes, int n_in,
                              void* d_out, int out_size) {
    const int*   inputs = (const int*)d_in[0];
    const int*   dirs   = (const int*)d_in[1];
    const int*   goal   = (const int*)d_in[2];
    const int*   locd   = (const int*)d_in[3];
    const float* pdr    = (const float*)d_in[4];
    const float* link   = (const float*)d_in[5];
    const float* dire   = (const float*)d_in[6];
    const float* w_ih   = (const float*)d_in[7];
    const float* b_ih   = (const float*)d_in[8];
    const float* w_hh   = (const float*)d_in[9];
    const float* b_hh   = (const float*)d_in[10];
    const float* W1     = (const float*)d_in[11];
    const float* b1     = (const float*)d_in[12];
    const float* W2     = (const float*)d_in[13];
    const float* b2     = (const float*)d_in[14];
    const float* W3     = (const float*)d_in[15];
    const float* b3     = (const float*)d_in[16];
    float* out = (float*)d_out;

    static int smem_set = 0;
    if (!smem_set) {
        cudaFuncSetAttribute(k_rnn, cudaFuncAttributeMaxDynamicSharedMemorySize, PK_SMEM);
        cudaFuncSetAttribute(k_pe, cudaFuncAttributeMaxDynamicSharedMemorySize, PE_SMEM);
        smem_set = 1;
    }

    // Fused prep: flags + fp16 splits + Q
    k_prep<<<1024, 256>>>(w_hh, w_ih, link, dire, b_ih, b_hh);

    // P = link_emb @ Wih_link^T (fp16 2-term, 512 threads, 16 warps)
    k_pe<<<dim3(65, 32), 512, PE_SMEM>>>();

    // Persistent recurrence (round-13 exact)
    k_rnn<<<dim3(4, 32), 512, PK_SMEM>>>(inputs, dirs);

    k_mlp<<<dim3(BD / 32, HD / 32), 256>>>(0, W1, b1);
    k_mlp<<<dim3(BD / 32, HD / 32), 256>>>(1, W2, b2);
    k_logits<<<(BD * NDD + 255) / 256, 256>>>(W3, b3);
    k_head<<<1, BD>>>(inputs, goal, locd, link, dire, pdr, out);

    // Sim GEMM (fp32, round-13) + 5x tiling
    k_sim<<<dim3(NED / 64, BD / 64), 256>>>(link, out);
}

// round 17
// speedup vs baseline: 1.0555x; 1.0024x over previous
#include <cuda_runtime.h>
#include <cuda_fp16.h>
#include <math.h>
#include <stdint.h>

// Problem dims
#define BD   512
#define SD   128
#define NED  8192
#define EDD  128
#define DDD  32
#define IND  160
#define HD   512
#define G4D  2048
#define NDD  8
#define PLD  5

#define OUT_PRED_D (512u*8192u*5u)
#define OUT_LOSS   (OUT_PRED_D + 512u*8u*5u)
#define OUT_DC     (OUT_LOSS + 1u)

// ---------------- device scratch ----------------
__device__ float g_P[(NED+1)*G4D];
__device__ float g_Q[(NDD+1)*G4D];
__device__ __half g_whh_fhi[G4D*HD], g_whh_flo[G4D*HD];
__device__ __half g_hh[2][BD*HD], g_hl[2][BD*HD];
__device__ __half g_link_fhi[(NED+1)*EDD], g_link_flo[(NED+1)*EDD];
__device__ __half g_wih_fhi[G4D*EDD], g_wih_flo[G4D*EDD];
__device__ __half g_w1hi[HD*HD], g_w1lo[HD*HD];
__device__ __half g_w2hi[HD*HD], g_w2lo[HD*HD];
__device__ __half g_z1hi[BD*HD], g_z1lo[BD*HD];
__device__ float g_z2[BD*HD];
__device__ float g_logits[BD*NDD], g_query[BD*EDD];
__device__ volatile unsigned g_flag[4 * 32 * 32];

__device__ __forceinline__ float sigmf(float x) { return 1.0f / (1.0f + expf(-x)); }

__device__ __forceinline__ void h16_split(float v, __half& hi, __half& lo) {
    hi = __float2half_rn(v);
    float r = v - __half2float(hi);
    lo = __float2half_rn(r * 1024.0f);
}

__device__ __forceinline__ uint32_t smem_u32(const void* p) {
    uint32_t a;
    asm("{ .reg .u64 t; cvta.to.shared.u64 t, %1; cvt.u32.u64 %0, t; }" : "=r"(a) : "l"(p));
    return a;
}
__device__ __forceinline__ void cp16(uint32_t dst, const void* src) {
    asm volatile("cp.async.cg.shared.global [%0], [%1], 16;" :: "r"(dst), "l"(src));
}
__device__ __forceinline__ void ldsm4(uint32_t* r, uint32_t addr) {
    asm volatile("ldmatrix.sync.aligned.m8n8.x4.shared.b16 {%0,%1,%2,%3}, [%4];"
                 : "=r"(r[0]), "=r"(r[1]), "=r"(r[2]), "=r"(r[3]) : "r"(addr));
}
#define CP_COMMIT() asm volatile("cp.async.commit_group;" ::: "memory")
#define CP_WAIT0()  asm volatile("cp.async.wait_group 0;" ::: "memory")
#define CP_WAIT1()  asm volatile("cp.async.wait_group 1;" ::: "memory")
#define BARN(id, n) asm volatile("bar.sync %0, %1;" :: "r"(id), "r"(n) : "memory")

#define MMAH(d, a, b) \
    asm volatile("mma.sync.aligned.m16n8k16.row.col.f32.f16.f16.f32 " \
                 "{%0,%1,%2,%3},{%4,%5,%6,%7},{%8,%9},{%0,%1,%2,%3};" \
                 : "+f"(d[0]), "+f"(d[1]), "+f"(d[2]), "+f"(d[3]) \
                 : "r"(a[0]), "r"(a[1]), "r"(a[2]), "r"(a[3]), "r"(b[0]), "r"(b[1]))

// ---------------------------------------------------------------------------
// K-prep: fused flag init + fp16 splits (whh, wih, link, W1, W2) + Q build
// ---------------------------------------------------------------------------
__global__ void k_prep(const float* __restrict__ whh, const float* __restrict__ wih,
                       const float* __restrict__ link, const float* __restrict__ dire,
                       const float* __restrict__ bih, const float* __restrict__ bhh,
                       const float* __restrict__ W1, const float* __restrict__ W2) {
    int i = blockIdx.x * blockDim.x + threadIdx.x;
    int stride = gridDim.x * blockDim.x;
    if (i < 4 * 32 * 32) g_flag[i] = 0u;
    for (int idx = i; idx < G4D*HD; idx += stride) {
        __half hi, lo; h16_split(whh[idx], hi, lo);
        g_whh_fhi[idx] = hi; g_whh_flo[idx] = lo;
    }
    for (int idx = i; idx < G4D*EDD; idx += stride) {
        int n = idx >> 7, k = idx & 127;
        __half hi, lo; h16_split(wih[n * IND + k], hi, lo);
        g_wih_fhi[idx] = hi; g_wih_flo[idx] = lo;
    }
    for (int idx = i; idx < (NED+1)*EDD; idx += stride) {
        __half hi, lo; h16_split(link[idx], hi, lo);
        g_link_fhi[idx] = hi; g_link_flo[idx] = lo;
    }
    for (int idx = i; idx < HD*HD; idx += stride) {
        __half hi, lo;
        h16_split(W1[idx], hi, lo); g_w1hi[idx] = hi; g_w1lo[idx] = lo;
        h16_split(W2[idx], hi, lo); g_w2hi[idx] = hi; g_w2lo[idx] = lo;
    }
    for (int idx = i; idx < (NDD+1) * G4D; idx += stride) {
        int d = idx / G4D, n = idx - d * G4D;
        float acc = bih[n] + bhh[n];
#pragma unroll 8
        for (int k = 0; k < DDD; k++) acc += dire[d * DDD + k] * wih[n * IND + EDD + k];
        g_Q[idx] = acc;
    }
}

// ---------------------------------------------------------------------------
// K-pe (fp16 2-term, 512 threads / 16 warps, warp tile 32x16):
//   P = link_emb @ Wih_link^T. M=8193, N=2048, K=128. CTA 128m x 64n.
// ---------------------------------------------------------------------------
#define PASTR 20
#define PA_LO 2560
#define PB_HI 5120
#define PB_LO 6400
#define PBUFW 7680
#define PE_SMEM (2 * PBUFW * 4)

__global__ void __launch_bounds__(512) k_pe() {
    extern __shared__ float psm[];
    const uint32_t sbase = smem_u32(psm);
    const int tid = threadIdx.x;
    const int lane = tid & 31, wid = tid >> 5;
    const int gid = lane >> 2, tig = lane & 3;
    const int mBase = blockIdx.x * 128, nBase = blockIdx.y * 64;
    const int warpM = (wid >> 2) * 32, warpN = (wid & 3) * 16;

    const uint32_t aOff = (uint32_t)(((warpM + (lane & 7) + ((lane >> 3) & 1) * 8) * PASTR
                                     + (lane >> 4) * 4) * 4);
    const uint32_t bOff = (uint32_t)(((warpN + (lane & 7) + ((lane >> 4) & 1) * 8) * PASTR
                                     + ((lane >> 3) & 1) * 4) * 4);

    float D[2][2][4], E[2][2][4];
#pragma unroll
    for (int mt = 0; mt < 2; mt++)
#pragma unroll
        for (int nt = 0; nt < 2; nt++)
#pragma unroll
            for (int r = 0; r < 4; r++) { D[mt][nt][r] = 0.f; E[mt][nt][r] = 0.f; }

    auto load = [&](int cc, int buf) {
        const int kb = cc * 32;
        const uint32_t bu = sbase + (uint32_t)buf * (PBUFW * 4);
#pragma unroll
        for (int t = 0; t < 3; t++) {
            int id = tid + t * 512;
            const __half* src;
            uint32_t dst;
            if (id < 1024) {
                int isLo = id >> 9, rem = id & 511;
                int r = rem >> 2, t4 = rem & 3;
                int rg = mBase + r; if (rg > NED) rg = NED;
                src = (isLo ? g_link_flo : g_link_fhi) + (size_t)rg * EDD + kb + t4 * 8;
                dst = bu + (uint32_t)(((isLo ? PA_LO : 0) + r * PASTR + t4 * 4) * 4);
            } else {
                int id2 = id - 1024;
                int isLo = id2 >> 8, rem = id2 & 255;
                int r = rem >> 2, t4 = rem & 3;
                src = (isLo ? g_wih_flo : g_wih_fhi) + (size_t)(nBase + r) * EDD + kb + t4 * 8;
                dst = bu + (uint32_t)(((isLo ? PB_LO : PB_HI) + r * PASTR + t4 * 4) * 4);
            }
            cp16(dst, src);
        }
        CP_COMMIT();
    };

    load(0, 0);
#pragma unroll 1
    for (int cc = 0; cc < 4; cc++) {
        const int buf = cc & 1;
        CP_WAIT0();
        __syncthreads();
        if (cc < 3) load(cc + 1, buf ^ 1);

        const uint32_t bb = sbase + (uint32_t)buf * (PBUFW * 4);
        const uint32_t aHi = bb + aOff, aLo = bb + (uint32_t)(PA_LO * 4) + aOff;
        const uint32_t bHi = bb + (uint32_t)(PB_HI * 4) + bOff;
        const uint32_t bLo = bb + (uint32_t)(PB_LO * 4) + bOff;
#pragma unroll
        for (int ksub = 0; ksub < 2; ksub++) {
            const uint32_t k0 = (uint32_t)(ksub * 8 * 4);
            uint32_t ahi[2][4], alo[2][4];
            ldsm4(ahi[0], aHi + k0);
            ldsm4(ahi[1], aHi + k0 + 16 * PASTR * 4);
            ldsm4(alo[0], aLo + k0);
            ldsm4(alo[1], aLo + k0 + 16 * PASTR * 4);
            uint32_t bhi[2][2], blo[2][2];
            {
                uint32_t t4[4];
                ldsm4(t4, bHi + k0);
                bhi[0][0] = t4[0]; bhi[0][1] = t4[1]; bhi[1][0] = t4[2]; bhi[1][1] = t4[3];
                ldsm4(t4, bLo + k0);
                blo[0][0] = t4[0]; blo[0][1] = t4[1]; blo[1][0] = t4[2]; blo[1][1] = t4[3];
            }
#pragma unroll
            for (int mt = 0; mt < 2; mt++)
#pragma unroll
                for (int nt = 0; nt < 2; nt++) {
                    MMAH(D[mt][nt], ahi[mt], bhi[nt]);
                    MMAH(E[mt][nt], ahi[mt], blo[nt]);
                    MMAH(E[mt][nt], alo[mt], bhi[nt]);
                }
        }
    }

#pragma unroll
    for (int mt = 0; mt < 2; mt++)
#pragma unroll
        for (int nt = 0; nt < 2; nt++) {
            int r0 = mBase + warpM + mt * 16 + gid;
            int n0 = nBase + warpN + nt * 8 + 2 * tig;
            float v0 = D[mt][nt][0] + E[mt][nt][0] * 0.0009765625f;
            float v1 = D[mt][nt][1] + E[mt][nt][1] * 0.0009765625f;
            float v2 = D[mt][nt][2] + E[mt][nt][2] * 0.0009765625f;
            float v3 = D[mt][nt][3] + E[mt][nt][3] * 0.0009765625f;
            if (r0 < NED + 1) {
                g_P[(size_t)r0 * G4D + n0]     = v0;
                g_P[(size_t)r0 * G4D + n0 + 1] = v1;
            }
            if (r0 + 8 < NED + 1) {
                g_P[(size_t)(r0+8) * G4D + n0]   = v2;
                g_P[(size_t)(r0+8) * G4D + n0+1] = v3;
            }
        }
}

// ---------------------------------------------------------------------------
// K-rnn: persistent recurrence (EXACT round-13 structure)
// ---------------------------------------------------------------------------
#define BSTR 260
#define BW_LO 16640
#define AW0   33280
#define AKG   10240
#define ABUF  5120
#define A_LOW 2560
#define ASTR  20
#define PK_SMEM (53760 * 4)

__global__ void __launch_bounds__(512, 1) k_rnn(const int* __restrict__ inputs,
                                                const int* __restrict__ dirs) {
    extern __shared__ float sm[];
    uint32_t* smw = (uint32_t*)sm;
    const uint32_t sbase = smem_u32(sm);
    const int tid = threadIdx.x;
    const int lane = tid & 31, wid = tid >> 5;
    const int kg = wid >> 3, wid8 = wid & 7;
    const int lt = tid & 255;
    const int grp = blockIdx.x;
    const int jt = blockIdx.y;
    const int bBase = blockIdx.x * 128;
    const int jBase = blockIdx.y * 16;
    const int warpM = (wid8 >> 1) * 32, warpN = (wid8 & 1) * 32;

    for (int i = tid; i < 64 * 64; i += 512) {
        int r = i >> 6, q = i & 63;
        int g = r & 3, jl = r >> 2;
        size_t src = ((size_t)(g * HD + jBase + jl)) * HD + q * 8;
        uint4 vh = *(const uint4*)(g_whh_fhi + src);
        uint4 vl = *(const uint4*)(g_whh_flo + src);
        *(uint4*)(smw + r * BSTR + q * 4) = vh;
        *(uint4*)(smw + BW_LO + r * BSTR + q * 4) = vl;
    }
    __syncthreads();

    const uint32_t aOffL = (uint32_t)(((warpM + (lane & 7) + ((lane >> 3) & 1) * 8) * ASTR
                                      + (lane >> 4) * 4) * 4);
    const uint32_t bOffL = (uint32_t)(((warpN + (lane & 7) + ((lane >> 4) & 1) * 8) * BSTR
                                      + ((lane >> 3) & 1) * 4) * 4);
    const uint32_t bHiL = sbase + bOffL;
    const uint32_t bLoL = sbase + (uint32_t)(BW_LO * 4) + bOffL;

    const int bl_ep = tid >> 2;
    const int b_ep = bBase + bl_ep;
    const int j0 = (tid & 3) * 4;
    float cst[4] = {0.f, 0.f, 0.f, 0.f};

    for (int s = 0; s < SD; s++) {
        const int inp = inputs[b_ep * SD + s];
        const int dr  = dirs[b_ep * SD + s];
        float gb[16];
#pragma unroll
        for (int g = 0; g < 4; g++) {
            float4 pv = *(const float4*)(g_P + (size_t)inp * G4D + g * HD + jBase + j0);
            float4 qv = *(const float4*)(g_Q + (size_t)dr * G4D + g * HD + jBase + j0);
            gb[g * 4 + 0] = pv.x + qv.x;
            gb[g * 4 + 1] = pv.y + qv.y;
            gb[g * 4 + 2] = pv.z + qv.z;
            gb[g * 4 + 3] = pv.w + qv.w;
        }

        float D[2][4][4], E[2][4][4];
#pragma unroll
        for (int mt = 0; mt < 2; mt++)
#pragma unroll
            for (int nt = 0; nt < 4; nt++)
#pragma unroll
                for (int r = 0; r < 4; r++) { D[mt][nt][r] = 0.f; E[mt][nt][r] = 0.f; }

        if (s > 0) {
            const __half* __restrict__ hh = g_hh[s & 1];
            const __half* __restrict__ hl = g_hl[s & 1];
            auto load_chunk = [&](int cc, int buf) {
                const int kb = kg * 256 + cc * 32;
                const uint32_t bu = sbase + (uint32_t)((AW0 + kg * AKG + buf * ABUF) * 4);
#pragma unroll
                for (int t = 0; t < 4; t++) {
                    int id = lt + t * 256;
                    int isLo = id >> 9;
                    int rem = id & 511;
                    int r = rem >> 2, t4 = rem & 3;
                    const __half* src = (isLo ? hl : hh) + (size_t)(bBase + r) * HD + kb + t4 * 8;
                    uint32_t dst = bu + (uint32_t)(((isLo ? A_LOW : 0) + r * ASTR + t4 * 4) * 4);
                    cp16(dst, src);
                }
                CP_COMMIT();
            };

            load_chunk(0, 0);
#pragma unroll 1
            for (int cc = 0; cc < 8; cc++) {
                const int buf = cc & 1;
                BARN(1 + kg, 256);
                if (cc < 7) {
                    load_chunk(cc + 1, buf ^ 1);
                    CP_WAIT1();
                } else {
                    CP_WAIT0();
                }
                BARN(3 + kg, 256);

                const uint32_t aHiBase = sbase + (uint32_t)((AW0 + kg * AKG + buf * ABUF) * 4) + aOffL;
                const uint32_t aLoBase = aHiBase + (uint32_t)(A_LOW * 4);
                const int kwBase = kg * 128 + cc * 16;
#pragma unroll
                for (int ksub = 0; ksub < 2; ksub++) {
                    const int k0 = ksub * 8;
                    uint32_t ahi[2][4], alo[2][4];
                    ldsm4(ahi[0], aHiBase + k0 * 4);
                    ldsm4(ahi[1], aHiBase + k0 * 4 + 16 * ASTR * 4);
                    ldsm4(alo[0], aLoBase + k0 * 4);
                    ldsm4(alo[1], aLoBase + k0 * 4 + 16 * ASTR * 4);
                    uint32_t bhi[4][2], blo[4][2];
                    {
                        const uint32_t kwb = (uint32_t)((kwBase + k0) * 4);
                        uint32_t t4[4];
                        ldsm4(t4, bHiL + kwb);
                        bhi[0][0] = t4[0]; bhi[0][1] = t4[1]; bhi[1][0] = t4[2]; bhi[1][1] = t4[3];
                        ldsm4(t4, bHiL + kwb + 16 * BSTR * 4);
                        bhi[2][0] = t4[0]; bhi[2][1] = t4[1]; bhi[3][0] = t4[2]; bhi[3][1] = t4[3];
                        ldsm4(t4, bLoL + kwb);
                        blo[0][0] = t4[0]; blo[0][1] = t4[1]; blo[1][0] = t4[2]; blo[1][1] = t4[3];
                        ldsm4(t4, bLoL + kwb + 16 * BSTR * 4);
                        blo[2][0] = t4[0]; blo[2][1] = t4[1]; blo[3][0] = t4[2]; blo[3][1] = t4[3];
                    }
#pragma unroll
                    for (int mt = 0; mt < 2; mt++)
#pragma unroll
                        for (int nt = 0; nt < 4; nt++) {
                            MMAH(D[mt][nt], ahi[mt], bhi[nt]);
                            MMAH(E[mt][nt], ahi[mt], blo[nt]);
                            MMAH(E[mt][nt], alo[mt], bhi[nt]);
                        }
                }
            }
#pragma unroll
            for (int mt = 0; mt < 2; mt++)
#pragma unroll
                for (int nt = 0; nt < 4; nt++)
#pragma unroll
                    for (int r = 0; r < 4; r++)
                        D[mt][nt][r] += E[mt][nt][r] * 0.0009765625f;
        }

        __syncthreads();
        float* red = sm + AW0;
        if (s > 0) {
            const int gid = lane >> 2, tig = lane & 3;
            if (kg == 1) {
#pragma unroll
                for (int mt = 0; mt < 2; mt++)
#pragma unroll
                    for (int nt = 0; nt < 4; nt++) {
                        int r0 = warpM + mt * 16 + gid;
                        int n0 = warpN + nt * 8 + 2 * tig;
                        red[r0 * 68 + n0]           = D[mt][nt][0];
                        red[r0 * 68 + n0 + 1]       = D[mt][nt][1];
                        red[(r0 + 8) * 68 + n0]     = D[mt][nt][2];
                        red[(r0 + 8) * 68 + n0 + 1] = D[mt][nt][3];
                    }
            }
            __syncthreads();
            if (kg == 0) {
#pragma unroll
                for (int mt = 0; mt < 2; mt++)
#pragma unroll
                    for (int nt = 0; nt < 4; nt++) {
                        int r0 = warpM + mt * 16 + gid;
                        int n0 = warpN + nt * 8 + 2 * tig;
                        red[r0 * 68 + n0]           += D[mt][nt][0];
                        red[r0 * 68 + n0 + 1]       += D[mt][nt][1];
                        red[(r0 + 8) * 68 + n0]     += D[mt][nt][2];
                        red[(r0 + 8) * 68 + n0 + 1] += D[mt][nt][3];
                    }
            }
            __syncthreads();
        }

        {
            __half hhi[4], hlo[4];
#pragma unroll
            for (int jj = 0; jj < 4; jj++) {
                float gi = gb[0 * 4 + jj];
                float gf = gb[1 * 4 + jj];
                float gg = gb[2 * 4 + jj];
                float go = gb[3 * 4 + jj];
                if (s > 0) {
                    int nb = (j0 + jj) * 4;
                    gi += red[bl_ep * 68 + nb + 0];
                    gf += red[bl_ep * 68 + nb + 1];
                    gg += red[bl_ep * 68 + nb + 2];
                    go += red[bl_ep * 68 + nb + 3];
                }
                float cn = sigmf(gf) * cst[jj] + sigmf(gi) * tanhf(gg);
                cst[jj] = cn;
                float h = sigmf(go) * tanhf(cn);
                h16_split(h, hhi[jj], hlo[jj]);
            }
            __half* hho = g_hh[(s + 1) & 1];
            __half* hlo_ = g_hl[(s + 1) & 1];
            size_t off = (size_t)b_ep * HD + jBase + j0;
            *(__half2*)(hho + off)     = __halves2half2(hhi[0], hhi[1]);
            *(__half2*)(hho + off + 2) = __halves2half2(hhi[2], hhi[3]);
            *(__half2*)(hlo_ + off)     = __halves2half2(hlo[0], hlo[1]);
            *(__half2*)(hlo_ + off + 2) = __halves2half2(hlo[2], hlo[3]);
        }

        __threadfence();
        __syncthreads();
        if (tid == 0) g_flag[(grp * 32 + jt) * 32] = (unsigned)(s + 1);
        if (tid < 32) {
            while (g_flag[(grp * 32 + tid) * 32] < (unsigned)(s + 1)) { }
        }
        __threadfence();
        __syncthreads();
    }
}

// ---------------------------------------------------------------------------
// K-mlpf (fp16 2-term tensor-core MLP layer): z = relu(A @ W^T + b)
//   M=512, N=512, K=512. CTA 128m x 64n -> grid (4,8). 256 threads, 8 warps.
//   which=0: A = h (g_hh[0]/g_hl[0]), W = W1, out -> z1 hi/lo fp16
//   which=1: A = z1 hi/lo,            W = W2, out -> g_z2 fp32
// ---------------------------------------------------------------------------
__global__ void __launch_bounds__(256, 1) k_mlpf(int which, const float* __restrict__ bias) {
    extern __shared__ float psm[];
    const uint32_t sbase = smem_u32(psm);
    const int tid = threadIdx.x;
    const int lane = tid & 31, wid = tid >> 5;
    const int gid = lane >> 2, tig = lane & 3;
    const int mBase = blockIdx.x * 128, nBase = blockIdx.y * 64;
    const int warpM = (wid >> 1) * 32, warpN = (wid & 1) * 32;

    const __half* __restrict__ Ahi = which ? g_z1hi : g_hh[0];
    const __half* __restrict__ Alo = which ? g_z1lo : g_hl[0];
    const __half* __restrict__ Whi = which ? g_w2hi : g_w1hi;
    const __half* __restrict__ Wlo = which ? g_w2lo : g_w1lo;

    const uint32_t aOff = (uint32_t)(((warpM + (lane & 7) + ((lane >> 3) & 1) * 8) * PASTR
                                     + (lane >> 4) * 4) * 4);
    const uint32_t bOff = (uint32_t)(((warpN + (lane & 7) + ((lane >> 4) & 1) * 8) * PASTR
                                     + ((lane >> 3) & 1) * 4) * 4);

    float D[2][4][4], E[2][4][4];
#pragma unroll
    for (int mt = 0; mt < 2; mt++)
#pragma unroll
        for (int nt = 0; nt < 4; nt++)
#pragma unroll
            for (int r = 0; r < 4; r++) { D[mt][nt][r] = 0.f; E[mt][nt][r] = 0.f; }

    auto load = [&](int cc, int buf) {
        const int kb = cc * 32;
        const uint32_t bu = sbase + (uint32_t)buf * (PBUFW * 4);
#pragma unroll
        for (int t = 0; t < 6; t++) {
            int id = tid + t * 256;
            const __half* src;
            uint32_t dst;
            if (id < 1024) {
                int isLo = id >> 9, rem = id & 511;
                int r = rem >> 2, t4 = rem & 3;
                src = (isLo ? Alo : Ahi) + (size_t)(mBase + r) * HD + kb + t4 * 8;
                dst = bu + (uint32_t)(((isLo ? PA_LO : 0) + r * PASTR + t4 * 4) * 4);
            } else {
                int id2 = id - 1024;
                int isLo = id2 >> 8, rem = id2 & 255;
                int r = rem >> 2, t4 = rem & 3;
                src = (isLo ? Wlo : Whi) + (size_t)(nBase + r) * HD + kb + t4 * 8;
                dst = bu + (uint32_t)(((isLo ? PB_LO : PB_HI) + r * PASTR + t4 * 4) * 4);
            }
            cp16(dst, src);
        }
        CP_COMMIT();
    };

    load(0, 0);
#pragma unroll 1
    for (int cc = 0; cc < 16; cc++) {
        const int buf = cc & 1;
        CP_WAIT0();
        __syncthreads();
        if (cc < 15) load(cc + 1, buf ^ 1);

        const uint32_t bb = sbase + (uint32_t)buf * (PBUFW * 4);
        const uint32_t aHi = bb + aOff, aLo = bb + (uint32_t)(PA_LO * 4) + aOff;
        const uint32_t bHi = bb + (uint32_t)(PB_HI * 4) + bOff;
        const uint32_t bLo = bb + (uint32_t)(PB_LO * 4) + bOff;
#pragma unroll
        for (int ksub = 0; ksub < 2; ksub++) {
            const uint32_t k0 = (uint32_t)(ksub * 8 * 4);
            uint32_t ahi[2][4], alo[2][4];
            ldsm4(ahi[0], aHi + k0);
            ldsm4(ahi[1], aHi + k0 + 16 * PASTR * 4);
            ldsm4(alo[0], aLo + k0);
            ldsm4(alo[1], aLo + k0 + 16 * PASTR * 4);
            uint32_t bhi[4][2], blo[4][2];
            {
                uint32_t t4[4];
                ldsm4(t4, bHi + k0);
                bhi[0][0] = t4[0]; bhi[0][1] = t4[1]; bhi[1][0] = t4[2]; bhi[1][1] = t4[3];
                ldsm4(t4, bHi + k0 + 16 * PASTR * 4);
                bhi[2][0] = t4[0]; bhi[2][1] = t4[1]; bhi[3][0] = t4[2]; bhi[3][1] = t4[3];
                ldsm4(t4, bLo + k0);
                blo[0][0] = t4[0]; blo[0][1] = t4[1]; blo[1][0] = t4[2]; blo[1][1] = t4[3];
                ldsm4(t4, bLo + k0 + 16 * PASTR * 4);
                blo[2][0] = t4[0]; blo[2][1] = t4[1]; blo[3][0] = t4[2]; blo[3][1] = t4[3];
            }
#pragma unroll
            for (int mt = 0; mt < 2; mt++)
#pragma unroll
                for (int nt = 0; nt < 4; nt++) {
                    MMAH(D[mt][nt], ahi[mt], bhi[nt]);
                    MMAH(E[mt][nt], ahi[mt], blo[nt]);
                    MMAH(E[mt][nt], alo[mt], bhi[nt]);
                }
        }
    }

#pragma unroll
    for (int mt = 0; mt < 2; mt++)
#pragma unroll
        for (int nt = 0; nt < 4; nt++) {
            int r0 = mBase + warpM + mt * 16 + gid;
            int n0 = nBase + warpN + nt * 8 + 2 * tig;
            float b0 = bias[n0], b1v = bias[n0 + 1];
            float v0 = fmaxf(D[mt][nt][0] + E[mt][nt][0] * 0.0009765625f + b0, 0.0f);
            float v1 = fmaxf(D[mt][nt][1] + E[mt][nt][1] * 0.0009765625f + b1v, 0.0f);
            float v2 = fmaxf(D[mt][nt][2] + E[mt][nt][2] * 0.0009765625f + b0, 0.0f);
            float v3 = fmaxf(D[mt][nt][3] + E[mt][nt][3] * 0.0009765625f + b1v, 0.0f);
            if (which == 0) {
                __half h0, l0, h1, l1, h2, l2, h3, l3;
                h16_split(v0, h0, l0); h16_split(v1, h1, l1);
                h16_split(v2, h2, l2); h16_split(v3, h3, l3);
                *(__half2*)(g_z1hi + (size_t)r0 * HD + n0)       = __halves2half2(h0, h1);
                *(__half2*)(g_z1lo + (size_t)r0 * HD + n0)       = __halves2half2(l0, l1);
                *(__half2*)(g_z1hi + (size_t)(r0 + 8) * HD + n0) = __halves2half2(h2, h3);
                *(__half2*)(g_z1lo + (size_t)(r0 + 8) * HD + n0) = __halves2half2(l2, l3);
            } else {
                *(float2*)(g_z2 + (size_t)r0 * HD + n0)       = make_float2(v0, v1);
                *(float2*)(g_z2 + (size_t)(r0 + 8) * HD + n0) = make_float2(v2, v3);
            }
        }
}

__global__ void k_logits(const float* __restrict__ W3, const float* __restrict__ b3) {
    int idx = blockIdx.x * blockDim.x + threadIdx.x;
    if (idx >= BD * NDD) return;
    int b = idx >> 3, n = idx & 7;
    const float4* z = (const float4*)(g_z2 + b * HD);
    const float4* w = (const float4*)(W3 + n * HD);
    float acc = b3[n];
#pragma unroll 4
    for (int k = 0; k < HD / 4; k++) {
        float4 zv = z[k], wv = w[k];
        acc += zv.x * wv.x + zv.y * wv.y + zv.z * wv.z + zv.w * wv.w;
    }
    g_logits[idx] = acc;
}

// ---------------------------------------------------------------------------
// Head
// ---------------------------------------------------------------------------
__global__ void k_head(const int* __restrict__ inputs, const int* __restrict__ goal,
                       const int* __restrict__ locd, const float* __restrict__ link,
                       const float* __restrict__ dire, const float* __restrict__ pdr,
                       float* __restrict__ out) {
    int b = threadIdx.x;
    float p[NDD];
    float mx = -1e30f;
#pragma unroll
    for (int n = 0; n < NDD; n++) { p[n] = g_logits[b * NDD + n]; mx = fmaxf(mx, p[n]); }
    float se = 0.0f;
#pragma unroll
    for (int n = 0; n < NDD; n++) se += expf(p[n] - mx);
    float lse = mx + logf(se);
#pragma unroll
    for (int n = 0; n < NDD; n++) p[n] -= lse;

    float mx2 = -1e30f;
#pragma unroll
    for (int n = 0; n < NDD; n++) mx2 = fmaxf(mx2, p[n]);
    float se2 = 0.0f;
#pragma unroll
    for (int n = 0; n < NDD; n++) se2 += expf(p[n] - mx2);
    float lse2 = mx2 + logf(se2);

    int i0 = 0; float v0 = p[0];
#pragma unroll
    for (int n = 1; n < NDD; n++) if (p[n] > v0) { v0 = p[n]; i0 = n; }
    int i1 = -1; float v1 = -1e30f;
#pragma unroll
    for (int n = 0; n < NDD; n++) if (n != i0 && p[n] > v1) { v1 = p[n]; i1 = n; }

    int last = inputs[b * SD + SD - 1];
    int lbl = locd[(size_t)(last - 1) * NED + goal[b]];
    float lossi = -(p[lbl] - lse2);
    int corr = (i0 == lbl) || (i1 == lbl);

    const float* le = link + (size_t)last * EDD;
    const float* d0 = dire + (i0 + 1) * DDD;
    const float* d1 = dire + (i1 + 1) * DDD;
#pragma unroll 4
    for (int k = 0; k < EDD; k++) {
        float q = le[k];
        if (k < DDD) q += 0.5f * (d0[k] + d1[k]);
        g_query[b * EDD + k] = q;
    }

    __shared__ float sl[BD];
    __shared__ int sc[BD];
    sl[b] = lossi; sc[b] = corr;
    __syncthreads();
    for (int st = BD / 2; st > 0; st >>= 1) {
        if (b < st) { sl[b] += sl[b + st]; sc[b] += sc[b + st]; }
        __syncthreads();
    }
    if (b == 0) {
        out[OUT_LOSS] = sl[0] * (5.0f / (float)BD);
        out[OUT_DC] = (float)sc[0];
    }
    for (int i = b; i < BD * NDD * PLD; i += BD) out[OUT_PRED_D + i] = pdr[i];
}

// ---------------------------------------------------------------------------
// Sim GEMM (fp32)
// ---------------------------------------------------------------------------
__global__ void k_sim(const float* __restrict__ link, float* __restrict__ out) {
    __shared__ float sq[64][17];
    __shared__ float sl[16][65];
    const int tid = threadIdx.x;
    const int tx = tid & 15, ty = tid >> 4;
    const int eBase = blockIdx.x * 64;
    const int mBase = blockIdx.y * 64;

    float acc[16];
#pragma unroll
    for (int i = 0; i < 16; i++) acc[i] = 0.0f;

    for (int kb = 0; kb < EDD; kb += 16) {
#pragma unroll
        for (int i = 0; i < 4; i++) {
            int idx = tid + i * 256;
            int r = idx >> 4, c = idx & 15;
            sq[r][c] = g_query[(mBase + r) * EDD + kb + c];
            sl[c][r] = link[((size_t)(eBase + r + 1)) * EDD + kb + c];
        }
        __syncthreads();
#pragma unroll
        for (int kk = 0; kk < 16; kk++) {
            float a0 = sq[ty][kk],      a1 = sq[ty + 16][kk];
            float a2 = sq[ty + 32][kk], a3 = sq[ty + 48][kk];
            float w0 = sl[kk][tx],      w1 = sl[kk][tx + 16];
            float w2 = sl[kk][tx + 32], w3 = sl[kk][tx + 48];
            acc[0]  += a0 * w0; acc[1]  += a0 * w1; acc[2]  += a0 * w2; acc[3]  += a0 * w3;
            acc[4]  += a1 * w0; acc[5]  += a1 * w1; acc[6]  += a1 * w2; acc[7]  += a1 * w3;
            acc[8]  += a2 * w0; acc[9]  += a2 * w1; acc[10] += a2 * w2; acc[11] += a2 * w3;
            acc[12] += a3 * w0; acc[13] += a3 * w1; acc[14] += a3 * w2; acc[15] += a3 * w3;
        }
        __syncthreads();
    }
#pragma unroll
    for (int mi = 0; mi < 4; mi++)
#pragma unroll
        for (int ni = 0; ni < 4; ni++) {
            int b = mBase + ty + mi * 16;
            int e = eBase + tx + ni * 16;
            float v = acc[mi * 4 + ni];
            size_t base = (size_t)b * (NED * PLD) + e;
#pragma unroll
            for (int pl = 0; pl < PLD; pl++) out[base + (size_t)pl * NED] = v;
        }
}

// ---------------------------------------------------------------------------
// Launcher
// ---------------------------------------------------------------------------
extern "C" void kernel_launch(void* const* d_in, const int* in_sizes, int n_in,
                              void* d_out, int out_size) {
    const int*   inputs = (const int*)d_in[0];
    const int*   dirs   = (const int*)d_in[1];
    const int*   goal   = (const int*)d_in[2];
    const int*   locd   = (const int*)d_in[3];
    const float* pdr    = (const float*)d_in[4];
    const float* link   = (const float*)d_in[5];
    const float* dire   = (const float*)d_in[6];
    const float* w_ih   = (const float*)d_in[7];
    const float* b_ih   = (const float*)d_in[8];
    const float* w_hh   = (const float*)d_in[9];
    const float* b_hh   = (const float*)d_in[10];
    const float* W1     = (const float*)d_in[11];
    const float* b1     = (const float*)d_in[12];
    const float* W2     = (const float*)d_in[13];
    const float* b2     = (const float*)d_in[14];
    const float* W3     = (const float*)d_in[15];
    const float* b3     = (const float*)d_in[16];
    float* out = (float*)d_out;

    static int smem_set = 0;
    if (!smem_set) {
        cudaFuncSetAttribute(k_rnn, cudaFuncAttributeMaxDynamicSharedMemorySize, PK_SMEM);
        cudaFuncSetAttribute(k_pe, cudaFuncAttributeMaxDynamicSharedMemorySize, PE_SMEM);
        cudaFuncSetAttribute(k_mlpf, cudaFuncAttributeMaxDynamicSharedMemorySize, PE_SMEM);
        smem_set = 1;
    }

    // Fused prep: flags + fp16 splits (incl. W1/W2) + Q
    k_prep<<<1024, 256>>>(w_hh, w_ih, link, dire, b_ih, b_hh, W1, W2);

    // P = link_emb @ Wih_link^T (fp16 2-term, 512 threads)
    k_pe<<<dim3(65, 32), 512, PE_SMEM>>>();

    // Persistent recurrence (final h fp16 split lands in g_hh[0]/g_hl[0])
    k_rnn<<<dim3(4, 32), 512, PK_SMEM>>>(inputs, dirs);

    // MLP head via fp16 2-term tensor cores
    k_mlpf<<<dim3(4, 8), 256, PE_SMEM>>>(0, b1);
    k_mlpf<<<dim3(4, 8), 256, PE_SMEM>>>(1, b2);
    k_logits<<<(BD * NDD + 255) / 256, 256>>>(W3, b3);
    k_head<<<1, BD>>>(inputs, goal, locd, link, dire, pdr, out);

    // Sim GEMM (fp32) + 5x tiling
    k_sim<<<dim3(NED / 64, BD / 64), 256>>>(link, out);
}